// round 3
// baseline (speedup 1.0000x reference)
#include <cuda_runtime.h>
#include <cuda_bf16.h>

#define BATCH 32
#define CIN   256
#define CC    64
#define PT    196     // 14*14
#define HT    14
#define PS    4096    // 64*64
#define HS    64
#define NGROUP 32     // groups of 2 channels

typedef unsigned long long ull;

// ---------------- packed f32x2 helpers (FFMA2 on sm_103a) -------------------
__device__ __forceinline__ ull fma2(ull a, ull b, ull c) {
    ull d;
    asm("fma.rn.f32x2 %0, %1, %2, %3;" : "=l"(d) : "l"(a), "l"(b), "l"(c));
    return d;
}
__device__ __forceinline__ ull pack2(float lo, float hi) {
    ull d;
    asm("mov.b64 %0, {%1, %2};" : "=l"(d) : "f"(lo), "f"(hi));
    return d;
}
__device__ __forceinline__ float2 unpack2(ull v) {
    float2 r;
    asm("mov.b64 {%0, %1}, %2;" : "=f"(r.x), "=f"(r.y) : "l"(v));
    return r;
}
__device__ __forceinline__ void wreduce2(float& s, float& ss) {
    #pragma unroll
    for (int off = 16; off > 0; off >>= 1) {
        s  += __shfl_down_sync(0xffffffffu, s,  off);
        ss += __shfl_down_sync(0xffffffffu, ss, off);
    }
}

// ---------------- scratch (device globals; allocation-free) ----------------
__device__ float g_sraw[(size_t)BATCH*CC*PS];   // raw search conv1x1 (pre-GN)
__device__ float g_corr[(size_t)BATCH*CC*PS];   // global+local correlation
__device__ float g_y   [(size_t)BATCH*CC*PS];   // conv3x3 output (pre-GN)
__device__ float g_tker[(size_t)BATCH*CC*49];   // pooled 7x7 template kernels
__device__ float g_tglob[(size_t)BATCH*CC];     // template global means
__device__ float g_smean[BATCH*NGROUP];
__device__ float g_srstd[BATCH*NGROUP];
__device__ float g_pmean[BATCH*NGROUP];
__device__ float g_prstd[BATCH*NGROUP];
__device__ float2 g_p0[16*32*32];               // sgemm stats partials [strip][b][g]
__device__ float2 g_p1[512*8*8];                // conv3 stats partials [tile*32+b][warp][pp]

// ---------------- 1) template branch: conv1x1 + GN + relu + pools ----------
__global__ void k_template(const float* __restrict__ tf, const float* __restrict__ wt,
                           const float* __restrict__ gw, const float* __restrict__ gb) {
    int b = blockIdx.x, g = blockIdx.y;
    __shared__ float tv[392];
    __shared__ ull  wsm[256];            // (w[2g][ci], w[2g+1][ci])
    __shared__ float r1[128], r2[128];
    __shared__ float s_mean, s_rstd;
    int tid = threadIdx.x;
    const float* x = tf + (size_t)b * CIN * PT;

    for (int i = tid; i < 256; i += 128)
        wsm[i] = pack2(wt[(g * 2) * CIN + i], wt[(g * 2 + 1) * CIN + i]);
    __syncthreads();

    for (int p = tid; p < PT; p += 128) {
        ull acc = 0ull;
        #pragma unroll 4
        for (int ci = 0; ci < CIN; ci++) {
            float xv = x[ci * PT + p];
            acc = fma2(wsm[ci], pack2(xv, xv), acc);
        }
        float2 r = unpack2(acc);
        tv[p] = r.x; tv[PT + p] = r.y;
    }
    __syncthreads();

    float s = 0.f, ss = 0.f;
    for (int idx = tid; idx < 392; idx += 128) { float v = tv[idx]; s += v; ss += v * v; }
    r1[tid] = s; r2[tid] = ss;
    __syncthreads();
    for (int o = 64; o > 0; o >>= 1) {
        if (tid < o) { r1[tid] += r1[tid + o]; r2[tid] += r2[tid + o]; }
        __syncthreads();
    }
    if (tid == 0) {
        float m = r1[0] * (1.f / 392.f);
        float var = r2[0] * (1.f / 392.f) - m * m;
        s_mean = m; s_rstd = rsqrtf(var + 1e-5f);
    }
    __syncthreads();

    for (int idx = tid; idx < 392; idx += 128) {
        int c = idx / PT;
        float v = (tv[idx] - s_mean) * s_rstd * gw[g * 2 + c] + gb[g * 2 + c];
        tv[idx] = fmaxf(v, 0.f);
    }
    __syncthreads();

    if (tid < 98) {
        int c = tid / 49, cell = tid - c * 49;
        int i = cell / 7, j = cell - i * 7;
        int base = c * PT + (2 * i) * HT + 2 * j;
        float v = 0.25f * (tv[base] + tv[base + 1] + tv[base + HT] + tv[base + HT + 1]);
        g_tker[((size_t)b * CC + g * 2 + c) * 49 + cell] = v;
    }
    if (tid < 2) {
        float acc = 0.f;
        for (int p = 0; p < PT; p++) acc += tv[tid * PT + p];
        g_tglob[(size_t)b * CC + g * 2 + tid] = acc * (1.f / 196.f);
    }
}

// ---------------- 2) search conv1x1 GEMM, 64 outs x 256 px per block -------
// grid (16 strips of 256 px, 32 batch), 256 threads; thread: 8 outs x 8 px.
// A duplicated in smem -> broadcast LDS.64, zero packs in inner loop.
__global__ void __launch_bounds__(256) k_sgemm(const float* __restrict__ sf,
                                               const float* __restrict__ ws) {
    int b = blockIdx.y;
    int p0 = blockIdx.x * 256;
    __shared__ ull  Asd[16][64];    // (w,w) pairs
    __shared__ float Bs[16][256];
    int tid = threadIdx.x;
    int w = tid >> 5;               // warp 0..7 -> outs w*8..+7
    int lane = tid & 31;
    int to = w * 8;

    ull acc2[8][4];
    #pragma unroll
    for (int i = 0; i < 8; i++)
        #pragma unroll
        for (int j = 0; j < 4; j++) acc2[i][j] = 0ull;

    const float* xb = sf + (size_t)b * CIN * PS + p0;

    for (int k0 = 0; k0 < CIN; k0 += 16) {
        __syncthreads();
        for (int i = tid; i < 1024; i += 256) {
            int o = i >> 4, k = i & 15;
            float wv = ws[o * CIN + k0 + k];
            Asd[k][o] = pack2(wv, wv);
        }
        for (int i = tid; i < 1024; i += 256) {
            int k = i >> 6, p4 = i & 63;
            ((float4*)Bs[k])[p4] = ((const float4*)(xb + (size_t)(k0 + k) * PS))[p4];
        }
        __syncthreads();
        #pragma unroll
        for (int k = 0; k < 16; k++) {
            ull bq[4];
            #pragma unroll
            for (int q = 0; q < 4; q++)
                bq[q] = *(const ull*)&Bs[k][2 * lane + 64 * q];
            #pragma unroll
            for (int oo = 0; oo < 8; oo++) {
                ull a = Asd[k][to + oo];
                #pragma unroll
                for (int q = 0; q < 4; q++)
                    acc2[oo][q] = fma2(a, bq[q], acc2[oo][q]);
            }
        }
    }

    // write results (pairs at p = p0 + 64q + 2*lane)
    #pragma unroll
    for (int oo = 0; oo < 8; oo++) {
        float* dst = g_sraw + ((size_t)b * CC + to + oo) * PS + p0 + 2 * lane;
        #pragma unroll
        for (int q = 0; q < 4; q++) {
            float2 u = unpack2(acc2[oo][q]);
            *(float2*)(dst + 64 * q) = u;
        }
    }

    // fused GN stats partials: group gg covers outs (to+2gg, to+2gg+1)
    #pragma unroll
    for (int gg = 0; gg < 4; gg++) {
        float s = 0.f, ss = 0.f;
        #pragma unroll
        for (int oo = 2 * gg; oo < 2 * gg + 2; oo++)
            #pragma unroll
            for (int q = 0; q < 4; q++) {
                float2 u = unpack2(acc2[oo][q]);
                s += u.x + u.y; ss += u.x * u.x + u.y * u.y;
            }
        wreduce2(s, ss);
        if (lane == 0)
            g_p0[((size_t)blockIdx.x * 32 + b) * 32 + w * 4 + gg] = make_float2(s, ss);
    }
}

// ---------------- 3) reduce sgemm partials -> smean/srstd ------------------
__global__ void k_red0() {
    int i = blockIdx.x * 256 + threadIdx.x;
    if (i >= 1024) return;
    int b = i >> 5, g = i & 31;
    float s = 0.f, ss = 0.f;
    for (int st = 0; st < 16; st++) {
        float2 v = g_p0[((size_t)st * 32 + b) * 32 + g];
        s += v.x; ss += v.y;
    }
    float m = s * (1.f / 8192.f);
    float var = ss * (1.f / 8192.f) - m * m;
    g_smean[i] = m; g_srstd[i] = rsqrtf(var + 1e-5f);
}

// ---------------- 4) corr = global + 7x7 depthwise local (A/B parity) ------
// grid (4 strips of 16x64, 64 ch, 32 batch), 128 threads, 8 px per thread
#define CW 74
__global__ void __launch_bounds__(128) k_corr(const float* __restrict__ gnw,
                                              const float* __restrict__ gnb) {
    int strip = blockIdx.x, c = blockIdx.y, b = blockIdx.z;
    int ty0 = strip * 16;
    __shared__ float sm[22 * CW];
    __shared__ ull kwd[49];
    int tid = threadIdx.x;
    int bg = b * NGROUP + (c >> 1);
    float mean = g_smean[bg], rstd = g_srstd[bg];
    float gamma = gnw[c], beta = gnb[c];
    float tg = g_tglob[(size_t)b * CC + c];
    const float* src = g_sraw + ((size_t)b * CC + c) * PS;

    // tile: smem idx xx <-> global col gx = xx-4 (pad 4 keeps pair parity even)
    for (int i = tid; i < 22 * CW; i += 128) {
        int yy = i / CW, xx = i - yy * CW;
        int gy = ty0 + yy - 3, gx = xx - 4;
        float v = 0.f;
        if ((unsigned)gy < 64u && (unsigned)gx < 64u) {
            float r = src[gy * HS + gx];
            v = fmaxf((r - mean) * rstd * gamma + beta, 0.f);
        }
        sm[i] = v;
    }
    if (tid < 49) {
        float wv = g_tker[((size_t)b * CC + c) * 49 + tid];
        kwd[tid] = pack2(wv, wv);
    }
    __syncthreads();

    int row = tid >> 3;            // 0..15
    int j0 = (tid & 7) * 4;        // pair base -> px cols 2*j0 .. 2*j0+7
    ull A[4]  = {0ull, 0ull, 0ull, 0ull};
    ull Bv[5] = {0ull, 0ull, 0ull, 0ull, 0ull};

    #pragma unroll
    for (int ky = 0; ky < 7; ky++) {
        const ull* eg = (const ull*)&sm[(row + ky) * CW];
        ull e[8];
        #pragma unroll
        for (int i = 0; i < 8; i++) e[i] = eg[j0 + i];
        const ull* kr = &kwd[ky * 7];
        ull w1 = kr[1], w3 = kr[3], w5 = kr[5];
        #pragma unroll
        for (int j = 0; j < 4; j++) {
            A[j] = fma2(w1, e[j + 1], A[j]);
            A[j] = fma2(w3, e[j + 2], A[j]);
            A[j] = fma2(w5, e[j + 3], A[j]);
        }
        ull w0 = kr[0], w2 = kr[2], w4 = kr[4], w6 = kr[6];
        #pragma unroll
        for (int t = 0; t < 5; t++) {
            Bv[t] = fma2(w0, e[t],     Bv[t]);
            Bv[t] = fma2(w2, e[t + 1], Bv[t]);
            Bv[t] = fma2(w4, e[t + 2], Bv[t]);
            Bv[t] = fma2(w6, e[t + 3], Bv[t]);
        }
    }

    // recombine + global-corr term (center row = smem row row+3)
    const ull* egc = (const ull*)&sm[(row + 3) * CW];
    float out[8];
    #pragma unroll
    for (int j = 0; j < 4; j++) {
        float2 a   = unpack2(A[j]);
        float2 bj  = unpack2(Bv[j]);
        float2 bj1 = unpack2(Bv[j + 1]);
        float2 gc  = unpack2(egc[j0 + j + 2]);
        out[2 * j]     = a.x + bj.y  + tg * gc.x;
        out[2 * j + 1] = a.y + bj1.x + tg * gc.y;
    }

    float* dst = g_corr + ((size_t)b * CC + c) * PS + (ty0 + row) * HS + 2 * j0;
    *(float4*)dst       = make_float4(out[0], out[1], out[2], out[3]);
    *(float4*)(dst + 4) = make_float4(out[4], out[5], out[6], out[7]);
}

// ---------------- 5) conv3x3 (64->64), ch-pair FMA2, duplicated x tile -----
// grid (16 tiles of 16x16 px, 32 batch), 256 threads; 8 ch-pairs x 4 px.
__global__ void __launch_bounds__(256) k_conv3(const float* __restrict__ wp1) {
    int tile = blockIdx.x, b = blockIdx.y;
    int ty0 = (tile >> 2) * 16, tx0 = (tile & 3) * 16;
    __shared__ float xs[8][18][38];   // duplicated: x at col gx stored at 2*(gx_local+1), +1
    __shared__ float wsm[8][9][68];   // [ci][k][o], consecutive o -> LDS.64 pairs
    int tid = threadIdx.x;
    int ty = tid >> 6;                 // 0..3 -> outs ty*16..+15
    int tx = tid & 63;
    int r  = tx >> 2;                  // pixel row 0..15
    int c0 = (tx & 3) * 4;             // pixel col base

    ull acc2[8][4];
    #pragma unroll
    for (int i = 0; i < 8; i++)
        #pragma unroll
        for (int j = 0; j < 4; j++) acc2[i][j] = 0ull;

    for (int cc0 = 0; cc0 < CC; cc0 += 8) {
        __syncthreads();
        for (int i = tid; i < 8 * 324; i += 256) {
            int ci = i / 324; int rem = i - ci * 324;
            int yy = rem / 18, xx = rem - yy * 18;
            int gy = ty0 + yy - 1, gx = tx0 + xx - 1;
            float v = 0.f;
            if ((unsigned)gy < 64u && (unsigned)gx < 64u)
                v = g_corr[((size_t)b * CC + cc0 + ci) * PS + gy * HS + gx];
            *(float2*)&xs[ci][yy][2 * xx] = make_float2(v, v);
        }
        for (int i = tid; i < 8 * 9 * 64; i += 256) {
            int o = i / 72; int rem = i - o * 72;
            int ci = rem / 9, k = rem - ci * 9;
            wsm[ci][k][o] = wp1[o * (CC * 9) + (cc0 + ci) * 9 + k];
        }
        __syncthreads();

        #pragma unroll 2
        for (int ci = 0; ci < 8; ci++) {
            #pragma unroll
            for (int dy = 0; dy < 3; dy++) {
                ull xb[6];
                #pragma unroll
                for (int i = 0; i < 6; i++)
                    xb[i] = *(const ull*)&xs[ci][r + dy][2 * (c0 + i)];
                #pragma unroll
                for (int dx = 0; dx < 3; dx++) {
                    const ull* wrow = (const ull*)&wsm[ci][dy * 3 + dx][ty * 16];
                    #pragma unroll
                    for (int pp = 0; pp < 8; pp++) {
                        ull w = wrow[pp];
                        acc2[pp][0] = fma2(w, xb[dx],     acc2[pp][0]);
                        acc2[pp][1] = fma2(w, xb[dx + 1], acc2[pp][1]);
                        acc2[pp][2] = fma2(w, xb[dx + 2], acc2[pp][2]);
                        acc2[pp][3] = fma2(w, xb[dx + 3], acc2[pp][3]);
                    }
                }
            }
        }
    }

    #pragma unroll
    for (int pp = 0; pp < 8; pp++) {
        float2 u0 = unpack2(acc2[pp][0]), u1 = unpack2(acc2[pp][1]);
        float2 u2 = unpack2(acc2[pp][2]), u3 = unpack2(acc2[pp][3]);
        int o0 = ty * 16 + 2 * pp;
        float* dst0 = g_y + ((size_t)b * CC + o0) * PS + (ty0 + r) * HS + tx0 + c0;
        *(float4*)dst0        = make_float4(u0.x, u1.x, u2.x, u3.x);
        *(float4*)(dst0 + PS) = make_float4(u0.y, u1.y, u2.y, u3.y);
    }

    // fused GN stats partials: pp = channel pair = GN group (ty*8+pp)
    int w = tid >> 5;   // warp id; ty uniform within warp
    #pragma unroll
    for (int pp = 0; pp < 8; pp++) {
        float s = 0.f, ss = 0.f;
        #pragma unroll
        for (int j = 0; j < 4; j++) {
            float2 u = unpack2(acc2[pp][j]);
            s += u.x + u.y; ss += u.x * u.x + u.y * u.y;
        }
        wreduce2(s, ss);
        if ((tid & 31) == 0)
            g_p1[(((size_t)tile * 32 + b) * 8 + w) * 8 + pp] = make_float2(s, ss);
    }
}

// ---------------- 6) reduce conv3 partials -> pmean/prstd ------------------
__global__ void k_red1() {
    int i = blockIdx.x * 256 + threadIdx.x;
    if (i >= 1024) return;
    int b = i >> 5, g = i & 31;
    int ty = g >> 3, pp = g & 7;
    float s = 0.f, ss = 0.f;
    for (int tile = 0; tile < 16; tile++) {
        #pragma unroll
        for (int wi = 0; wi < 2; wi++) {
            float2 v = g_p1[(((size_t)tile * 32 + b) * 8 + 2 * ty + wi) * 8 + pp];
            s += v.x; ss += v.y;
        }
    }
    float m = s * (1.f / 8192.f);
    float var = ss * (1.f / 8192.f) - m * m;
    g_pmean[i] = m; g_prstd[i] = rsqrtf(var + 1e-5f);
}

// ---------------- 7) final: GN + relu + 1x1 conv to 1 channel (float4) -----
__global__ void k_final(const float* __restrict__ gnw, const float* __restrict__ gnb,
                        const float* __restrict__ w2, const float* __restrict__ b2,
                        float* __restrict__ out) {
    int idx = blockIdx.x * 256 + threadIdx.x;   // 32768 threads, 4 px each
    if (idx >= BATCH * PS / 4) return;
    int b = idx >> 10, p4 = idx & 1023;
    const float4* yb = (const float4*)(g_y + (size_t)b * CC * PS) + p4;
    float bias = b2[0];
    float4 acc = make_float4(bias, bias, bias, bias);
    #pragma unroll 4
    for (int o = 0; o < CC; o++) {
        int bg = b * NGROUP + (o >> 1);
        float m = g_pmean[bg], rs = g_prstd[bg];
        float ga = gnw[o] * rs, be = gnb[o] - m * gnw[o] * rs;
        float wv = w2[o];
        float4 v = yb[(size_t)o * (PS / 4)];
        acc.x += wv * fmaxf(v.x * ga + be, 0.f);
        acc.y += wv * fmaxf(v.y * ga + be, 0.f);
        acc.z += wv * fmaxf(v.z * ga + be, 0.f);
        acc.w += wv * fmaxf(v.w * ga + be, 0.f);
    }
    ((float4*)out)[idx] = acc;
}

// ---------------- launch ----------------------------------------------------
extern "C" void kernel_launch(void* const* d_in, const int* in_sizes, int n_in,
                              void* d_out, int out_size) {
    const float* template_feat = (const float*)d_in[0];
    const float* search_feat   = (const float*)d_in[1];
    const float* w_t    = (const float*)d_in[2];
    const float* gn_t_w = (const float*)d_in[3];
    const float* gn_t_b = (const float*)d_in[4];
    const float* w_s    = (const float*)d_in[5];
    const float* gn_s_w = (const float*)d_in[6];
    const float* gn_s_b = (const float*)d_in[7];
    const float* w_p1   = (const float*)d_in[8];
    const float* gn_p_w = (const float*)d_in[9];
    const float* gn_p_b = (const float*)d_in[10];
    const float* w_p2   = (const float*)d_in[11];
    const float* b_p2   = (const float*)d_in[12];
    float* out = (float*)d_out;

    k_template<<<dim3(BATCH, NGROUP), 128>>>(template_feat, w_t, gn_t_w, gn_t_b);
    k_sgemm<<<dim3(16, BATCH), 256>>>(search_feat, w_s);
    k_red0<<<4, 256>>>();
    k_corr<<<dim3(4, CC, BATCH), 128>>>(gn_s_w, gn_s_b);
    k_conv3<<<dim3(16, BATCH), 256>>>(w_p1);
    k_red1<<<4, 256>>>();
    k_final<<<128, 256>>>(gn_p_w, gn_p_b, w_p2, b_p2, out);
}

// round 4
// speedup vs baseline: 1.5187x; 1.5187x over previous
#include <cuda_runtime.h>
#include <cuda_bf16.h>

#define BATCH 32
#define CIN   256
#define CC    64
#define PT    196     // 14*14
#define HT    14
#define PS    4096    // 64*64
#define HS    64
#define NGROUP 32     // groups of 2 channels

typedef unsigned long long ull;

// ---------------- packed f32x2 helpers (FFMA2 on sm_103a) -------------------
__device__ __forceinline__ ull fma2(ull a, ull b, ull c) {
    ull d;
    asm("fma.rn.f32x2 %0, %1, %2, %3;" : "=l"(d) : "l"(a), "l"(b), "l"(c));
    return d;
}
__device__ __forceinline__ ull pack2(float lo, float hi) {
    ull d;
    asm("mov.b64 %0, {%1, %2};" : "=l"(d) : "f"(lo), "f"(hi));
    return d;
}
__device__ __forceinline__ float2 unpack2(ull v) {
    float2 r;
    asm("mov.b64 {%0, %1}, %2;" : "=f"(r.x), "=f"(r.y) : "l"(v));
    return r;
}

// ---------------- scratch (device globals; allocation-free) ----------------
__device__ float g_sraw[(size_t)BATCH*CC*PS];   // raw search conv1x1 (pre-GN)
__device__ float g_corr[(size_t)BATCH*CC*PS];   // global+local correlation
__device__ float g_y   [(size_t)BATCH*CC*PS];   // conv3x3 output (pre-GN)
__device__ float g_tker[(size_t)BATCH*CC*49];   // pooled 7x7 template kernels
__device__ float g_tglob[(size_t)BATCH*CC];     // template global means
__device__ float g_smean[BATCH*NGROUP];
__device__ float g_srstd[BATCH*NGROUP];
__device__ float g_pmean[BATCH*NGROUP];
__device__ float g_prstd[BATCH*NGROUP];

// ---------------- 1) template branch: conv1x1 + GN + relu + pools ----------
// grid (32 batch, 32 group), 128 threads. FMA2 packs the 2 group channels.
__global__ void k_template(const float* __restrict__ tf, const float* __restrict__ wt,
                           const float* __restrict__ gw, const float* __restrict__ gb) {
    int b = blockIdx.x, g = blockIdx.y;
    __shared__ float tv[392];
    __shared__ ull  wsm[256];            // (w[2g][ci], w[2g+1][ci])
    __shared__ float r1[128], r2[128];
    __shared__ float s_mean, s_rstd;
    int tid = threadIdx.x;
    const float* x = tf + (size_t)b * CIN * PT;

    for (int i = tid; i < 256; i += 128)
        wsm[i] = pack2(wt[(g * 2) * CIN + i], wt[(g * 2 + 1) * CIN + i]);
    __syncthreads();

    for (int p = tid; p < PT; p += 128) {
        ull acc = 0ull;
        #pragma unroll 4
        for (int ci = 0; ci < CIN; ci++) {
            float xv = x[ci * PT + p];
            acc = fma2(wsm[ci], pack2(xv, xv), acc);
        }
        float2 r = unpack2(acc);
        tv[p] = r.x; tv[PT + p] = r.y;
    }
    __syncthreads();

    float s = 0.f, ss = 0.f;
    for (int idx = tid; idx < 392; idx += 128) { float v = tv[idx]; s += v; ss += v * v; }
    r1[tid] = s; r2[tid] = ss;
    __syncthreads();
    for (int o = 64; o > 0; o >>= 1) {
        if (tid < o) { r1[tid] += r1[tid + o]; r2[tid] += r2[tid + o]; }
        __syncthreads();
    }
    if (tid == 0) {
        float m = r1[0] * (1.f / 392.f);
        float var = r2[0] * (1.f / 392.f) - m * m;
        s_mean = m; s_rstd = rsqrtf(var + 1e-5f);
    }
    __syncthreads();

    for (int idx = tid; idx < 392; idx += 128) {
        int c = idx / PT;
        float v = (tv[idx] - s_mean) * s_rstd * gw[g * 2 + c] + gb[g * 2 + c];
        tv[idx] = fmaxf(v, 0.f);
    }
    __syncthreads();

    if (tid < 98) {
        int c = tid / 49, cell = tid - c * 49;
        int i = cell / 7, j = cell - i * 7;
        int base = c * PT + (2 * i) * HT + 2 * j;
        float v = 0.25f * (tv[base] + tv[base + 1] + tv[base + HT] + tv[base + HT + 1]);
        g_tker[((size_t)b * CC + g * 2 + c) * 49 + cell] = v;
    }
    if (tid < 2) {
        float acc = 0.f;
        for (int p = 0; p < PT; p++) acc += tv[tid * PT + p];
        g_tglob[(size_t)b * CC + g * 2 + tid] = acc * (1.f / 196.f);
    }
}

// ---------------- 2) search conv1x1 GEMM: [64,256]x[256,4096] per batch ----
// grid (32 px-tiles of 128, 32 batch), 256 threads, 4 out x 8 px (4 px-pairs)
// A pre-duplicated in smem -> zero packs in the inner loop.
__global__ void __launch_bounds__(256) k_sgemm(const float* __restrict__ sf,
                                               const float* __restrict__ ws) {
    int b = blockIdx.y;
    int p0 = blockIdx.x * 128;
    __shared__ ull  Asd[16][64];    // (w,w) duplicated pairs [k][o]
    __shared__ float Bs[16][128];   // [k][p]
    int tid = threadIdx.x;
    int ty = tid >> 4;              // 0..15 -> outs ty*4..+3
    int tx = tid & 15;              // px tx*8..+7
    ull acc2[4][4];
    #pragma unroll
    for (int i = 0; i < 4; i++)
        #pragma unroll
        for (int j = 0; j < 4; j++) acc2[i][j] = 0ull;

    const float* xb = sf + (size_t)b * CIN * PS + p0;

    for (int k0 = 0; k0 < CIN; k0 += 16) {
        __syncthreads();
        for (int i = tid; i < 1024; i += 256) {
            int o = i >> 4, k = i & 15;
            float wv = ws[o * CIN + k0 + k];
            Asd[k][o] = pack2(wv, wv);
        }
        for (int i = tid; i < 512; i += 256) {
            int k = i >> 5, p4 = i & 31;
            ((float4*)Bs[k])[p4] =
                ((const float4*)(xb + (size_t)(k0 + k) * PS))[p4];
        }
        __syncthreads();
        #pragma unroll
        for (int k = 0; k < 16; k++) {
            ull ap0 = Asd[k][ty * 4];
            ull ap1 = Asd[k][ty * 4 + 1];
            ull ap2 = Asd[k][ty * 4 + 2];
            ull ap3 = Asd[k][ty * 4 + 3];
            const ull* bp = (const ull*)&Bs[k][tx * 8];
            ull b0 = bp[0], b1 = bp[1], b2 = bp[2], b3 = bp[3];
            acc2[0][0] = fma2(ap0, b0, acc2[0][0]);
            acc2[0][1] = fma2(ap0, b1, acc2[0][1]);
            acc2[0][2] = fma2(ap0, b2, acc2[0][2]);
            acc2[0][3] = fma2(ap0, b3, acc2[0][3]);
            acc2[1][0] = fma2(ap1, b0, acc2[1][0]);
            acc2[1][1] = fma2(ap1, b1, acc2[1][1]);
            acc2[1][2] = fma2(ap1, b2, acc2[1][2]);
            acc2[1][3] = fma2(ap1, b3, acc2[1][3]);
            acc2[2][0] = fma2(ap2, b0, acc2[2][0]);
            acc2[2][1] = fma2(ap2, b1, acc2[2][1]);
            acc2[2][2] = fma2(ap2, b2, acc2[2][2]);
            acc2[2][3] = fma2(ap2, b3, acc2[2][3]);
            acc2[3][0] = fma2(ap3, b0, acc2[3][0]);
            acc2[3][1] = fma2(ap3, b1, acc2[3][1]);
            acc2[3][2] = fma2(ap3, b2, acc2[3][2]);
            acc2[3][3] = fma2(ap3, b3, acc2[3][3]);
        }
    }
    #pragma unroll
    for (int i = 0; i < 4; i++) {
        int o = ty * 4 + i;
        float2 u0 = unpack2(acc2[i][0]), u1 = unpack2(acc2[i][1]);
        float2 u2 = unpack2(acc2[i][2]), u3 = unpack2(acc2[i][3]);
        float* dst = g_sraw + ((size_t)b * CC + o) * PS + p0 + tx * 8;
        *(float4*)dst       = make_float4(u0.x, u0.y, u1.x, u1.y);
        *(float4*)(dst + 4) = make_float4(u2.x, u2.y, u3.x, u3.y);
    }
}

// ---------------- 3/6) GN stats: per (b,group) over 2 channels x 4096 ------
__global__ void k_stats(int which) {
    const float* buf = which ? g_y : g_sraw;
    float* mean = which ? g_pmean : g_smean;
    float* rstd = which ? g_prstd : g_srstd;
    int bg = blockIdx.x;
    const float* x = buf + (size_t)bg * 2 * PS;
    int tid = threadIdx.x;
    float s = 0.f, ss = 0.f;
    for (int i = tid; i < 2 * PS; i += 256) { float v = x[i]; s += v; ss += v * v; }
    __shared__ float r1[256], r2[256];
    r1[tid] = s; r2[tid] = ss;
    __syncthreads();
    for (int o = 128; o > 0; o >>= 1) {
        if (tid < o) { r1[tid] += r1[tid + o]; r2[tid] += r2[tid + o]; }
        __syncthreads();
    }
    if (tid == 0) {
        float m = r1[0] * (1.f / (2.f * PS));
        float var = r2[0] * (1.f / (2.f * PS)) - m * m;
        mean[bg] = m; rstd[bg] = rsqrtf(var + 1e-5f);
    }
}

// ---------------- 4) corr = global + 7x7 depthwise local (R1 scalar) -------
// grid (4 tiles of 32x32, 64 ch, 32 batch), 256 threads, 4 px per thread
__global__ void __launch_bounds__(256) k_corr(const float* __restrict__ gnw,
                                              const float* __restrict__ gnb) {
    int tile = blockIdx.x, c = blockIdx.y, b = blockIdx.z;
    int ty0 = (tile >> 1) * 32, tx0 = (tile & 1) * 32;
    __shared__ float sm[38 * 38];
    __shared__ float kw[49];
    int tid = threadIdx.x;
    int bg = b * NGROUP + (c >> 1);
    float mean = g_smean[bg], rstd = g_srstd[bg];
    float gamma = gnw[c], beta = gnb[c];
    float tg = g_tglob[(size_t)b * CC + c];
    const float* src = g_sraw + ((size_t)b * CC + c) * PS;

    for (int i = tid; i < 38 * 38; i += 256) {
        int yy = i / 38, xx = i - yy * 38;
        int gy = ty0 + yy - 3, gx = tx0 + xx - 3;
        float v = 0.f;
        if ((unsigned)gy < 64u && (unsigned)gx < 64u) {
            float r = src[gy * HS + gx];
            v = fmaxf((r - mean) * rstd * gamma + beta, 0.f);
        }
        sm[i] = v;
    }
    if (tid < 49) kw[tid] = g_tker[((size_t)b * CC + c) * 49 + tid];
    __syncthreads();

    int p = tid * 4;
    int py = p >> 5, px = p & 31;
    float a0 = 0.f, a1 = 0.f, a2 = 0.f, a3 = 0.f;
    #pragma unroll
    for (int ky = 0; ky < 7; ky++) {
        const float* row = &sm[(py + ky) * 38 + px];
        #pragma unroll
        for (int kx = 0; kx < 7; kx++) {
            float w = kw[ky * 7 + kx];
            a0 += w * row[kx];
            a1 += w * row[kx + 1];
            a2 += w * row[kx + 2];
            a3 += w * row[kx + 3];
        }
    }
    const float* ctr = &sm[(py + 3) * 38 + px + 3];
    a0 += tg * ctr[0]; a1 += tg * ctr[1]; a2 += tg * ctr[2]; a3 += tg * ctr[3];

    float* dst = g_corr + ((size_t)b * CC + c) * PS + (ty0 + py) * HS + tx0 + px;
    *(float4*)dst = make_float4(a0, a1, a2, a3);
}

// ---------------- 5) conv3x3 (64->64), ch-pair FMA2 (R2 version) -----------
// grid (16 tiles of 16x16 px, 32 batch), 256 threads; 8 ch-pairs x 4 px.
__global__ void __launch_bounds__(256) k_conv3(const float* __restrict__ wp1) {
    int tile = blockIdx.x, b = blockIdx.y;
    int ty0 = (tile >> 2) * 16, tx0 = (tile & 3) * 16;
    __shared__ float xs[8][18][19];   // odd stride: conflict-free-ish
    __shared__ float wsm[8][9][68];   // [ci][k][o], consecutive o -> LDS.64 pairs
    int tid = threadIdx.x;
    int ty = tid >> 6;                 // 0..3 -> outs ty*16..+15
    int tx = tid & 63;
    int r  = tx >> 2;                  // pixel row 0..15
    int c0 = (tx & 3) * 4;             // pixel col base

    ull acc2[8][4];
    #pragma unroll
    for (int i = 0; i < 8; i++)
        #pragma unroll
        for (int j = 0; j < 4; j++) acc2[i][j] = 0ull;

    for (int cc0 = 0; cc0 < CC; cc0 += 8) {
        __syncthreads();
        for (int i = tid; i < 8 * 324; i += 256) {
            int ci = i / 324; int rem = i - ci * 324;
            int yy = rem / 18, xx = rem - yy * 18;
            int gy = ty0 + yy - 1, gx = tx0 + xx - 1;
            float v = 0.f;
            if ((unsigned)gy < 64u && (unsigned)gx < 64u)
                v = g_corr[((size_t)b * CC + cc0 + ci) * PS + gy * HS + gx];
            xs[ci][yy][xx] = v;
        }
        for (int i = tid; i < 8 * 9 * 64; i += 256) {
            int o = i / 72; int rem = i - o * 72;
            int ci = rem / 9, k = rem - ci * 9;
            wsm[ci][k][o] = wp1[o * (CC * 9) + (cc0 + ci) * 9 + k];
        }
        __syncthreads();

        #pragma unroll 2
        for (int ci = 0; ci < 8; ci++) {
            #pragma unroll
            for (int dy = 0; dy < 3; dy++) {
                float xr[6];
                #pragma unroll
                for (int i = 0; i < 6; i++) xr[i] = xs[ci][r + dy][c0 + i];
                ull xb[6];
                #pragma unroll
                for (int i = 0; i < 6; i++) xb[i] = pack2(xr[i], xr[i]);
                #pragma unroll
                for (int dx = 0; dx < 3; dx++) {
                    const ull* wrow = (const ull*)&wsm[ci][dy * 3 + dx][ty * 16];
                    #pragma unroll
                    for (int pp = 0; pp < 8; pp++) {
                        ull w = wrow[pp];
                        acc2[pp][0] = fma2(w, xb[dx],     acc2[pp][0]);
                        acc2[pp][1] = fma2(w, xb[dx + 1], acc2[pp][1]);
                        acc2[pp][2] = fma2(w, xb[dx + 2], acc2[pp][2]);
                        acc2[pp][3] = fma2(w, xb[dx + 3], acc2[pp][3]);
                    }
                }
            }
        }
    }
    #pragma unroll
    for (int pp = 0; pp < 8; pp++) {
        float2 u0 = unpack2(acc2[pp][0]), u1 = unpack2(acc2[pp][1]);
        float2 u2 = unpack2(acc2[pp][2]), u3 = unpack2(acc2[pp][3]);
        int o0 = ty * 16 + 2 * pp;
        float* dst0 = g_y + ((size_t)b * CC + o0) * PS + (ty0 + r) * HS + tx0 + c0;
        *(float4*)dst0        = make_float4(u0.x, u1.x, u2.x, u3.x);
        *(float4*)(dst0 + PS) = make_float4(u0.y, u1.y, u2.y, u3.y);
    }
}

// ---------------- 7) final: GN + relu + 1x1 conv to 1 channel (float4) -----
__global__ void k_final(const float* __restrict__ gnw, const float* __restrict__ gnb,
                        const float* __restrict__ w2, const float* __restrict__ b2,
                        float* __restrict__ out) {
    int idx = blockIdx.x * 256 + threadIdx.x;   // 32768 threads, 4 px each
    if (idx >= BATCH * PS / 4) return;
    int b = idx >> 10, p4 = idx & 1023;
    const float4* yb = (const float4*)(g_y + (size_t)b * CC * PS) + p4;
    float bias = b2[0];
    float4 acc = make_float4(bias, bias, bias, bias);
    #pragma unroll 4
    for (int o = 0; o < CC; o++) {
        int bg = b * NGROUP + (o >> 1);
        float m = g_pmean[bg], rs = g_prstd[bg];
        float ga = gnw[o] * rs, be = gnb[o] - m * gnw[o] * rs;
        float wv = w2[o];
        float4 v = yb[(size_t)o * (PS / 4)];
        acc.x += wv * fmaxf(v.x * ga + be, 0.f);
        acc.y += wv * fmaxf(v.y * ga + be, 0.f);
        acc.z += wv * fmaxf(v.z * ga + be, 0.f);
        acc.w += wv * fmaxf(v.w * ga + be, 0.f);
    }
    ((float4*)out)[idx] = acc;
}

// ---------------- launch ----------------------------------------------------
extern "C" void kernel_launch(void* const* d_in, const int* in_sizes, int n_in,
                              void* d_out, int out_size) {
    const float* template_feat = (const float*)d_in[0];
    const float* search_feat   = (const float*)d_in[1];
    const float* w_t    = (const float*)d_in[2];
    const float* gn_t_w = (const float*)d_in[3];
    const float* gn_t_b = (const float*)d_in[4];
    const float* w_s    = (const float*)d_in[5];
    const float* gn_s_w = (const float*)d_in[6];
    const float* gn_s_b = (const float*)d_in[7];
    const float* w_p1   = (const float*)d_in[8];
    const float* gn_p_w = (const float*)d_in[9];
    const float* gn_p_b = (const float*)d_in[10];
    const float* w_p2   = (const float*)d_in[11];
    const float* b_p2   = (const float*)d_in[12];
    float* out = (float*)d_out;

    k_template<<<dim3(BATCH, NGROUP), 128>>>(template_feat, w_t, gn_t_w, gn_t_b);
    k_sgemm<<<dim3(PS / 128, BATCH), 256>>>(search_feat, w_s);
    k_stats<<<BATCH * NGROUP, 256>>>(0);
    k_corr<<<dim3(4, CC, BATCH), 256>>>(gn_s_w, gn_s_b);
    k_conv3<<<dim3(16, BATCH), 256>>>(w_p1);
    k_stats<<<BATCH * NGROUP, 256>>>(1);
    k_final<<<128, 256>>>(gn_p_w, gn_p_b, w_p2, b_p2, out);
}

// round 5
// speedup vs baseline: 1.6595x; 1.0927x over previous
#include <cuda_runtime.h>
#include <cuda_bf16.h>

#define BATCH 32
#define CIN   256
#define CC    64
#define PT    196     // 14*14
#define HT    14
#define PS    4096    // 64*64
#define HS    64
#define NGROUP 32     // groups of 2 channels

typedef unsigned long long ull;

// ---------------- packed f32x2 helpers (FFMA2 on sm_103a) -------------------
__device__ __forceinline__ ull fma2(ull a, ull b, ull c) {
    ull d;
    asm("fma.rn.f32x2 %0, %1, %2, %3;" : "=l"(d) : "l"(a), "l"(b), "l"(c));
    return d;
}
__device__ __forceinline__ ull pack2(float lo, float hi) {
    ull d;
    asm("mov.b64 %0, {%1, %2};" : "=l"(d) : "f"(lo), "f"(hi));
    return d;
}
__device__ __forceinline__ float2 unpack2(ull v) {
    float2 r;
    asm("mov.b64 {%0, %1}, %2;" : "=f"(r.x), "=f"(r.y) : "l"(v));
    return r;
}

// ---------------- scratch (device globals; allocation-free) ----------------
__device__ float g_sraw[(size_t)BATCH*CC*PS];   // raw search conv1x1 (pre-GN)
__device__ float g_corr[(size_t)BATCH*CC*PS];   // global+local correlation
__device__ float g_y   [(size_t)BATCH*CC*PS];   // conv3x3 output (pre-GN)
__device__ float g_tker[(size_t)BATCH*CC*49];   // pooled 7x7 template kernels
__device__ float g_tglob[(size_t)BATCH*CC];     // template global means
__device__ float g_smean[BATCH*NGROUP];
__device__ float g_srstd[BATCH*NGROUP];
__device__ float g_pmean[BATCH*NGROUP];
__device__ float g_prstd[BATCH*NGROUP];
__device__ float2 g_p0[32*32*32];               // sgemm stats partials [strip][b][g]
__device__ float2 g_p1[512*8*8];                // conv3 stats partials [tile*32+b][warp][pp]

// ---------------- 1) template branch: conv1x1 + GN + relu + pools ----------
// grid (32 batch, 32 group), 128 threads. FMA2 packs the 2 group channels.
__global__ void k_template(const float* __restrict__ tf, const float* __restrict__ wt,
                           const float* __restrict__ gw, const float* __restrict__ gb) {
    int b = blockIdx.x, g = blockIdx.y;
    __shared__ float tv[392];
    __shared__ ull  wsm[256];            // (w[2g][ci], w[2g+1][ci])
    __shared__ float r1[128], r2[128];
    __shared__ float s_mean, s_rstd;
    int tid = threadIdx.x;
    const float* x = tf + (size_t)b * CIN * PT;

    for (int i = tid; i < 256; i += 128)
        wsm[i] = pack2(wt[(g * 2) * CIN + i], wt[(g * 2 + 1) * CIN + i]);
    __syncthreads();

    for (int p = tid; p < PT; p += 128) {
        ull acc = 0ull;
        #pragma unroll 4
        for (int ci = 0; ci < CIN; ci++) {
            float xv = x[ci * PT + p];
            acc = fma2(wsm[ci], pack2(xv, xv), acc);
        }
        float2 r = unpack2(acc);
        tv[p] = r.x; tv[PT + p] = r.y;
    }
    __syncthreads();

    float s = 0.f, ss = 0.f;
    for (int idx = tid; idx < 392; idx += 128) { float v = tv[idx]; s += v; ss += v * v; }
    r1[tid] = s; r2[tid] = ss;
    __syncthreads();
    for (int o = 64; o > 0; o >>= 1) {
        if (tid < o) { r1[tid] += r1[tid + o]; r2[tid] += r2[tid + o]; }
        __syncthreads();
    }
    if (tid == 0) {
        float m = r1[0] * (1.f / 392.f);
        float var = r2[0] * (1.f / 392.f) - m * m;
        s_mean = m; s_rstd = rsqrtf(var + 1e-5f);
    }
    __syncthreads();

    for (int idx = tid; idx < 392; idx += 128) {
        int c = idx / PT;
        float v = (tv[idx] - s_mean) * s_rstd * gw[g * 2 + c] + gb[g * 2 + c];
        tv[idx] = fmaxf(v, 0.f);
    }
    __syncthreads();

    if (tid < 98) {
        int c = tid / 49, cell = tid - c * 49;
        int i = cell / 7, j = cell - i * 7;
        int base = c * PT + (2 * i) * HT + 2 * j;
        float v = 0.25f * (tv[base] + tv[base + 1] + tv[base + HT] + tv[base + HT + 1]);
        g_tker[((size_t)b * CC + g * 2 + c) * 49 + cell] = v;
    }
    if (tid < 2) {
        float acc = 0.f;
        for (int p = 0; p < PT; p++) acc += tv[tid * PT + p];
        g_tglob[(size_t)b * CC + g * 2 + tid] = acc * (1.f / 196.f);
    }
}

// ---------------- 2) search conv1x1 GEMM (R2 form) + fused GN partials -----
// grid (32 px-tiles of 128, 32 batch), 256 threads, 4 out x 8 px (4 px-pairs)
__global__ void __launch_bounds__(256) k_sgemm(const float* __restrict__ sf,
                                               const float* __restrict__ ws) {
    int b = blockIdx.y;
    int p0 = blockIdx.x * 128;
    __shared__ float As[16][68];    // [k][o], padded
    __shared__ float Bs[16][128];   // [k][p]
    int tid = threadIdx.x;
    int ty = tid >> 4;              // 0..15 -> outs ty*4..+3
    int tx = tid & 15;              // px tx*8..+7
    ull acc2[4][4];
    #pragma unroll
    for (int i = 0; i < 4; i++)
        #pragma unroll
        for (int j = 0; j < 4; j++) acc2[i][j] = 0ull;

    const float* xb = sf + (size_t)b * CIN * PS + p0;

    for (int k0 = 0; k0 < CIN; k0 += 16) {
        __syncthreads();
        for (int i = tid; i < 1024; i += 256) {
            int o = i >> 4, k = i & 15;
            As[k][o] = ws[o * CIN + k0 + k];
        }
        for (int i = tid; i < 512; i += 256) {
            int k = i >> 5, p4 = i & 31;
            ((float4*)Bs[k])[p4] =
                ((const float4*)(xb + (size_t)(k0 + k) * PS))[p4];
        }
        __syncthreads();
        #pragma unroll
        for (int k = 0; k < 16; k++) {
            float4 a = *(const float4*)&As[k][ty * 4];
            ull ap0 = pack2(a.x, a.x), ap1 = pack2(a.y, a.y);
            ull ap2 = pack2(a.z, a.z), ap3 = pack2(a.w, a.w);
            const ull* bp = (const ull*)&Bs[k][tx * 8];
            ull b0 = bp[0], b1 = bp[1], b2 = bp[2], b3 = bp[3];
            acc2[0][0] = fma2(ap0, b0, acc2[0][0]);
            acc2[0][1] = fma2(ap0, b1, acc2[0][1]);
            acc2[0][2] = fma2(ap0, b2, acc2[0][2]);
            acc2[0][3] = fma2(ap0, b3, acc2[0][3]);
            acc2[1][0] = fma2(ap1, b0, acc2[1][0]);
            acc2[1][1] = fma2(ap1, b1, acc2[1][1]);
            acc2[1][2] = fma2(ap1, b2, acc2[1][2]);
            acc2[1][3] = fma2(ap1, b3, acc2[1][3]);
            acc2[2][0] = fma2(ap2, b0, acc2[2][0]);
            acc2[2][1] = fma2(ap2, b1, acc2[2][1]);
            acc2[2][2] = fma2(ap2, b2, acc2[2][2]);
            acc2[2][3] = fma2(ap2, b3, acc2[2][3]);
            acc2[3][0] = fma2(ap3, b0, acc2[3][0]);
            acc2[3][1] = fma2(ap3, b1, acc2[3][1]);
            acc2[3][2] = fma2(ap3, b2, acc2[3][2]);
            acc2[3][3] = fma2(ap3, b3, acc2[3][3]);
        }
    }
    #pragma unroll
    for (int i = 0; i < 4; i++) {
        int o = ty * 4 + i;
        float2 u0 = unpack2(acc2[i][0]), u1 = unpack2(acc2[i][1]);
        float2 u2 = unpack2(acc2[i][2]), u3 = unpack2(acc2[i][3]);
        float* dst = g_sraw + ((size_t)b * CC + o) * PS + p0 + tx * 8;
        *(float4*)dst       = make_float4(u0.x, u0.y, u1.x, u1.y);
        *(float4*)(dst + 4) = make_float4(u2.x, u2.y, u3.x, u3.y);
    }

    // fused GN stats partials: groups 2ty (outs ty*4,ty*4+1) and 2ty+1
    #pragma unroll
    for (int gg = 0; gg < 2; gg++) {
        float s = 0.f, ss = 0.f;
        #pragma unroll
        for (int i = 2 * gg; i < 2 * gg + 2; i++)
            #pragma unroll
            for (int j = 0; j < 4; j++) {
                float2 u = unpack2(acc2[i][j]);
                s += u.x + u.y; ss += u.x * u.x + u.y * u.y;
            }
        #pragma unroll
        for (int off = 8; off > 0; off >>= 1) {
            s  += __shfl_down_sync(0xffffffffu, s,  off, 16);
            ss += __shfl_down_sync(0xffffffffu, ss, off, 16);
        }
        if (tx == 0)
            g_p0[((size_t)blockIdx.x * 32 + b) * 32 + 2 * ty + gg] = make_float2(s, ss);
    }
}

// ---------------- 3) reduce sgemm partials -> smean/srstd ------------------
__global__ void k_red0() {
    int i = blockIdx.x * 256 + threadIdx.x;
    if (i >= 1024) return;
    int b = i >> 5, g = i & 31;
    float s = 0.f, ss = 0.f;
    #pragma unroll 4
    for (int st = 0; st < 32; st++) {
        float2 v = g_p0[((size_t)st * 32 + b) * 32 + g];
        s += v.x; ss += v.y;
    }
    float m = s * (1.f / 8192.f);
    float var = ss * (1.f / 8192.f) - m * m;
    g_smean[i] = m; g_srstd[i] = rsqrtf(var + 1e-5f);
}

// ---------------- 4) corr = global + 7x7 depthwise local (R1 scalar) -------
// grid (4 tiles of 32x32, 64 ch, 32 batch), 256 threads, 4 px per thread
__global__ void __launch_bounds__(256) k_corr(const float* __restrict__ gnw,
                                              const float* __restrict__ gnb) {
    int tile = blockIdx.x, c = blockIdx.y, b = blockIdx.z;
    int ty0 = (tile >> 1) * 32, tx0 = (tile & 1) * 32;
    __shared__ float sm[38 * 38];
    __shared__ float kw[49];
    int tid = threadIdx.x;
    int bg = b * NGROUP + (c >> 1);
    float mean = g_smean[bg], rstd = g_srstd[bg];
    float gamma = gnw[c], beta = gnb[c];
    float tg = g_tglob[(size_t)b * CC + c];
    const float* src = g_sraw + ((size_t)b * CC + c) * PS;

    for (int i = tid; i < 38 * 38; i += 256) {
        int yy = i / 38, xx = i - yy * 38;
        int gy = ty0 + yy - 3, gx = tx0 + xx - 3;
        float v = 0.f;
        if ((unsigned)gy < 64u && (unsigned)gx < 64u) {
            float r = src[gy * HS + gx];
            v = fmaxf((r - mean) * rstd * gamma + beta, 0.f);
        }
        sm[i] = v;
    }
    if (tid < 49) kw[tid] = g_tker[((size_t)b * CC + c) * 49 + tid];
    __syncthreads();

    int p = tid * 4;
    int py = p >> 5, px = p & 31;
    float a0 = 0.f, a1 = 0.f, a2 = 0.f, a3 = 0.f;
    #pragma unroll
    for (int ky = 0; ky < 7; ky++) {
        const float* row = &sm[(py + ky) * 38 + px];
        #pragma unroll
        for (int kx = 0; kx < 7; kx++) {
            float w = kw[ky * 7 + kx];
            a0 += w * row[kx];
            a1 += w * row[kx + 1];
            a2 += w * row[kx + 2];
            a3 += w * row[kx + 3];
        }
    }
    const float* ctr = &sm[(py + 3) * 38 + px + 3];
    a0 += tg * ctr[0]; a1 += tg * ctr[1]; a2 += tg * ctr[2]; a3 += tg * ctr[3];

    float* dst = g_corr + ((size_t)b * CC + c) * PS + (ty0 + py) * HS + tx0 + px;
    *(float4*)dst = make_float4(a0, a1, a2, a3);
}

// ---------------- 5) conv3x3 (64->64), ch-pair FMA2 + fused GN partials ----
// grid (16 tiles of 16x16 px, 32 batch), 256 threads; 8 ch-pairs x 4 px.
__global__ void __launch_bounds__(256) k_conv3(const float* __restrict__ wp1) {
    int tile = blockIdx.x, b = blockIdx.y;
    int ty0 = (tile >> 2) * 16, tx0 = (tile & 3) * 16;
    __shared__ float xs[8][18][19];   // odd stride: conflict-free-ish
    __shared__ float wsm[8][9][68];   // [ci][k][o], consecutive o -> LDS.64 pairs
    int tid = threadIdx.x;
    int ty = tid >> 6;                 // 0..3 -> outs ty*16..+15
    int tx = tid & 63;
    int r  = tx >> 2;                  // pixel row 0..15
    int c0 = (tx & 3) * 4;             // pixel col base

    ull acc2[8][4];
    #pragma unroll
    for (int i = 0; i < 8; i++)
        #pragma unroll
        for (int j = 0; j < 4; j++) acc2[i][j] = 0ull;

    for (int cc0 = 0; cc0 < CC; cc0 += 8) {
        __syncthreads();
        for (int i = tid; i < 8 * 324; i += 256) {
            int ci = i / 324; int rem = i - ci * 324;
            int yy = rem / 18, xx = rem - yy * 18;
            int gy = ty0 + yy - 1, gx = tx0 + xx - 1;
            float v = 0.f;
            if ((unsigned)gy < 64u && (unsigned)gx < 64u)
                v = g_corr[((size_t)b * CC + cc0 + ci) * PS + gy * HS + gx];
            xs[ci][yy][xx] = v;
        }
        for (int i = tid; i < 8 * 9 * 64; i += 256) {
            int o = i / 72; int rem = i - o * 72;
            int ci = rem / 9, k = rem - ci * 9;
            wsm[ci][k][o] = wp1[o * (CC * 9) + (cc0 + ci) * 9 + k];
        }
        __syncthreads();

        #pragma unroll 2
        for (int ci = 0; ci < 8; ci++) {
            #pragma unroll
            for (int dy = 0; dy < 3; dy++) {
                float xr[6];
                #pragma unroll
                for (int i = 0; i < 6; i++) xr[i] = xs[ci][r + dy][c0 + i];
                ull xb[6];
                #pragma unroll
                for (int i = 0; i < 6; i++) xb[i] = pack2(xr[i], xr[i]);
                #pragma unroll
                for (int dx = 0; dx < 3; dx++) {
                    const ull* wrow = (const ull*)&wsm[ci][dy * 3 + dx][ty * 16];
                    #pragma unroll
                    for (int pp = 0; pp < 8; pp++) {
                        ull w = wrow[pp];
                        acc2[pp][0] = fma2(w, xb[dx],     acc2[pp][0]);
                        acc2[pp][1] = fma2(w, xb[dx + 1], acc2[pp][1]);
                        acc2[pp][2] = fma2(w, xb[dx + 2], acc2[pp][2]);
                        acc2[pp][3] = fma2(w, xb[dx + 3], acc2[pp][3]);
                    }
                }
            }
        }
    }
    #pragma unroll
    for (int pp = 0; pp < 8; pp++) {
        float2 u0 = unpack2(acc2[pp][0]), u1 = unpack2(acc2[pp][1]);
        float2 u2 = unpack2(acc2[pp][2]), u3 = unpack2(acc2[pp][3]);
        int o0 = ty * 16 + 2 * pp;
        float* dst0 = g_y + ((size_t)b * CC + o0) * PS + (ty0 + r) * HS + tx0 + c0;
        *(float4*)dst0        = make_float4(u0.x, u1.x, u2.x, u3.x);
        *(float4*)(dst0 + PS) = make_float4(u0.y, u1.y, u2.y, u3.y);
    }

    // fused GN stats partials: pp = channel pair = GN group (ty*8+pp)
    int w = tid >> 5;   // warp id; ty uniform within warp
    #pragma unroll
    for (int pp = 0; pp < 8; pp++) {
        float s = 0.f, ss = 0.f;
        #pragma unroll
        for (int j = 0; j < 4; j++) {
            float2 u = unpack2(acc2[pp][j]);
            s += u.x + u.y; ss += u.x * u.x + u.y * u.y;
        }
        #pragma unroll
        for (int off = 16; off > 0; off >>= 1) {
            s  += __shfl_down_sync(0xffffffffu, s,  off);
            ss += __shfl_down_sync(0xffffffffu, ss, off);
        }
        if ((tid & 31) == 0)
            g_p1[(((size_t)tile * 32 + b) * 8 + w) * 8 + pp] = make_float2(s, ss);
    }
}

// ---------------- 6) reduce conv3 partials -> pmean/prstd ------------------
__global__ void k_red1() {
    int i = blockIdx.x * 256 + threadIdx.x;
    if (i >= 1024) return;
    int b = i >> 5, g = i & 31;
    int ty = g >> 3, pp = g & 7;
    float s = 0.f, ss = 0.f;
    for (int tile = 0; tile < 16; tile++) {
        #pragma unroll
        for (int wi = 0; wi < 2; wi++) {
            float2 v = g_p1[(((size_t)tile * 32 + b) * 8 + 2 * ty + wi) * 8 + pp];
            s += v.x; ss += v.y;
        }
    }
    float m = s * (1.f / 8192.f);
    float var = ss * (1.f / 8192.f) - m * m;
    g_pmean[i] = m; g_prstd[i] = rsqrtf(var + 1e-5f);
}

// ---------------- 7) final: GN + relu + 1x1 conv to 1 channel (float4) -----
__global__ void k_final(const float* __restrict__ gnw, const float* __restrict__ gnb,
                        const float* __restrict__ w2, const float* __restrict__ b2,
                        float* __restrict__ out) {
    int idx = blockIdx.x * 256 + threadIdx.x;   // 32768 threads, 4 px each
    if (idx >= BATCH * PS / 4) return;
    int b = idx >> 10, p4 = idx & 1023;
    const float4* yb = (const float4*)(g_y + (size_t)b * CC * PS) + p4;
    float bias = b2[0];
    float4 acc = make_float4(bias, bias, bias, bias);
    #pragma unroll 4
    for (int o = 0; o < CC; o++) {
        int bg = b * NGROUP + (o >> 1);
        float m = g_pmean[bg], rs = g_prstd[bg];
        float ga = gnw[o] * rs, be = gnb[o] - m * gnw[o] * rs;
        float wv = w2[o];
        float4 v = yb[(size_t)o * (PS / 4)];
        acc.x += wv * fmaxf(v.x * ga + be, 0.f);
        acc.y += wv * fmaxf(v.y * ga + be, 0.f);
        acc.z += wv * fmaxf(v.z * ga + be, 0.f);
        acc.w += wv * fmaxf(v.w * ga + be, 0.f);
    }
    ((float4*)out)[idx] = acc;
}

// ---------------- launch ----------------------------------------------------
extern "C" void kernel_launch(void* const* d_in, const int* in_sizes, int n_in,
                              void* d_out, int out_size) {
    const float* template_feat = (const float*)d_in[0];
    const float* search_feat   = (const float*)d_in[1];
    const float* w_t    = (const float*)d_in[2];
    const float* gn_t_w = (const float*)d_in[3];
    const float* gn_t_b = (const float*)d_in[4];
    const float* w_s    = (const float*)d_in[5];
    const float* gn_s_w = (const float*)d_in[6];
    const float* gn_s_b = (const float*)d_in[7];
    const float* w_p1   = (const float*)d_in[8];
    const float* gn_p_w = (const float*)d_in[9];
    const float* gn_p_b = (const float*)d_in[10];
    const float* w_p2   = (const float*)d_in[11];
    const float* b_p2   = (const float*)d_in[12];
    float* out = (float*)d_out;

    k_template<<<dim3(BATCH, NGROUP), 128>>>(template_feat, w_t, gn_t_w, gn_t_b);
    k_sgemm<<<dim3(PS / 128, BATCH), 256>>>(search_feat, w_s);
    k_red0<<<4, 256>>>();
    k_corr<<<dim3(4, CC, BATCH), 256>>>(gn_s_w, gn_s_b);
    k_conv3<<<dim3(16, BATCH), 256>>>(w_p1);
    k_red1<<<4, 256>>>();
    k_final<<<128, 256>>>(gn_p_w, gn_p_b, w_p2, b_p2, out);
}

// round 6
// speedup vs baseline: 1.7847x; 1.0755x over previous
#include <cuda_runtime.h>
#include <cuda_bf16.h>

#define BATCH 32
#define CIN   256
#define CC    64
#define PT    196     // 14*14
#define HT    14
#define PS    4096    // 64*64
#define HS    64
#define NGROUP 32     // groups of 2 channels

typedef unsigned long long ull;

// ---------------- packed f32x2 helpers (FFMA2 on sm_103a) -------------------
__device__ __forceinline__ ull fma2(ull a, ull b, ull c) {
    ull d;
    asm("fma.rn.f32x2 %0, %1, %2, %3;" : "=l"(d) : "l"(a), "l"(b), "l"(c));
    return d;
}
__device__ __forceinline__ ull pack2(float lo, float hi) {
    ull d;
    asm("mov.b64 %0, {%1, %2};" : "=l"(d) : "f"(lo), "f"(hi));
    return d;
}
__device__ __forceinline__ float2 unpack2(ull v) {
    float2 r;
    asm("mov.b64 {%0, %1}, %2;" : "=f"(r.x), "=f"(r.y) : "l"(v));
    return r;
}
__device__ __forceinline__ float to_tf32(float v) {
    unsigned u;
    asm("cvt.rna.tf32.f32 %0, %1;" : "=r"(u) : "f"(v));
    return __uint_as_float(u);
}
__device__ __forceinline__ void mma_tf32(float* c, const unsigned* a,
                                         unsigned b0, unsigned b1) {
    asm("mma.sync.aligned.m16n8k8.row.col.f32.tf32.tf32.f32 "
        "{%0,%1,%2,%3}, {%4,%5,%6,%7}, {%8,%9}, {%0,%1,%2,%3};"
        : "+f"(c[0]), "+f"(c[1]), "+f"(c[2]), "+f"(c[3])
        : "r"(a[0]), "r"(a[1]), "r"(a[2]), "r"(a[3]), "r"(b0), "r"(b1));
}

// ---------------- scratch (device globals; allocation-free) ----------------
__device__ float g_sraw[(size_t)BATCH*CC*PS];   // raw search conv1x1 (pre-GN)
__device__ float g_corr[(size_t)BATCH*CC*PS];   // global+local correlation
__device__ float g_y   [(size_t)BATCH*CC*PS];   // conv3x3 output (pre-GN)
__device__ float g_tker[(size_t)BATCH*CC*49];   // pooled 7x7 template kernels
__device__ float g_tglob[(size_t)BATCH*CC];     // template global means
__device__ float g_smean[BATCH*NGROUP];
__device__ float g_srstd[BATCH*NGROUP];
__device__ float g_pmean[BATCH*NGROUP];
__device__ float g_prstd[BATCH*NGROUP];
__device__ float2 g_p0[32*32*32];               // sgemm stats partials [strip][b][g]
__device__ float2 g_p1[512*16*16];              // conv3 stats partials [tile*32+b][warp][row]

// ---------------- 1) template branch: conv1x1 + GN + relu + pools ----------
__global__ void k_template(const float* __restrict__ tf, const float* __restrict__ wt,
                           const float* __restrict__ gw, const float* __restrict__ gb) {
    int b = blockIdx.x, g = blockIdx.y;
    __shared__ float tv[392];
    __shared__ ull  wsm[256];            // (w[2g][ci], w[2g+1][ci])
    __shared__ float r1[128], r2[128];
    __shared__ float s_mean, s_rstd;
    int tid = threadIdx.x;
    const float* x = tf + (size_t)b * CIN * PT;

    for (int i = tid; i < 256; i += 128)
        wsm[i] = pack2(wt[(g * 2) * CIN + i], wt[(g * 2 + 1) * CIN + i]);
    __syncthreads();

    for (int p = tid; p < PT; p += 128) {
        ull acc = 0ull;
        #pragma unroll 4
        for (int ci = 0; ci < CIN; ci++) {
            float xv = x[ci * PT + p];
            acc = fma2(wsm[ci], pack2(xv, xv), acc);
        }
        float2 r = unpack2(acc);
        tv[p] = r.x; tv[PT + p] = r.y;
    }
    __syncthreads();

    float s = 0.f, ss = 0.f;
    for (int idx = tid; idx < 392; idx += 128) { float v = tv[idx]; s += v; ss += v * v; }
    r1[tid] = s; r2[tid] = ss;
    __syncthreads();
    for (int o = 64; o > 0; o >>= 1) {
        if (tid < o) { r1[tid] += r1[tid + o]; r2[tid] += r2[tid + o]; }
        __syncthreads();
    }
    if (tid == 0) {
        float m = r1[0] * (1.f / 392.f);
        float var = r2[0] * (1.f / 392.f) - m * m;
        s_mean = m; s_rstd = rsqrtf(var + 1e-5f);
    }
    __syncthreads();

    for (int idx = tid; idx < 392; idx += 128) {
        int c = idx / PT;
        float v = (tv[idx] - s_mean) * s_rstd * gw[g * 2 + c] + gb[g * 2 + c];
        tv[idx] = fmaxf(v, 0.f);
    }
    __syncthreads();

    if (tid < 98) {
        int c = tid / 49, cell = tid - c * 49;
        int i = cell / 7, j = cell - i * 7;
        int base = c * PT + (2 * i) * HT + 2 * j;
        float v = 0.25f * (tv[base] + tv[base + 1] + tv[base + HT] + tv[base + HT + 1]);
        g_tker[((size_t)b * CC + g * 2 + c) * 49 + cell] = v;
    }
    if (tid < 2) {
        float acc = 0.f;
        for (int p = 0; p < PT; p++) acc += tv[tid * PT + p];
        g_tglob[(size_t)b * CC + g * 2 + tid] = acc * (1.f / 196.f);
    }
}

// ---------------- 2) search conv1x1 GEMM (R2 form) + fused GN partials -----
__global__ void __launch_bounds__(256) k_sgemm(const float* __restrict__ sf,
                                               const float* __restrict__ ws) {
    int b = blockIdx.y;
    int p0 = blockIdx.x * 128;
    __shared__ float As[16][68];    // [k][o], padded
    __shared__ float Bs[16][128];   // [k][p]
    int tid = threadIdx.x;
    int ty = tid >> 4;              // 0..15 -> outs ty*4..+3
    int tx = tid & 15;              // px tx*8..+7
    ull acc2[4][4];
    #pragma unroll
    for (int i = 0; i < 4; i++)
        #pragma unroll
        for (int j = 0; j < 4; j++) acc2[i][j] = 0ull;

    const float* xb = sf + (size_t)b * CIN * PS + p0;

    for (int k0 = 0; k0 < CIN; k0 += 16) {
        __syncthreads();
        for (int i = tid; i < 1024; i += 256) {
            int o = i >> 4, k = i & 15;
            As[k][o] = ws[o * CIN + k0 + k];
        }
        for (int i = tid; i < 512; i += 256) {
            int k = i >> 5, p4 = i & 31;
            ((float4*)Bs[k])[p4] =
                ((const float4*)(xb + (size_t)(k0 + k) * PS))[p4];
        }
        __syncthreads();
        #pragma unroll
        for (int k = 0; k < 16; k++) {
            float4 a = *(const float4*)&As[k][ty * 4];
            ull ap0 = pack2(a.x, a.x), ap1 = pack2(a.y, a.y);
            ull ap2 = pack2(a.z, a.z), ap3 = pack2(a.w, a.w);
            const ull* bp = (const ull*)&Bs[k][tx * 8];
            ull b0 = bp[0], b1 = bp[1], b2 = bp[2], b3 = bp[3];
            acc2[0][0] = fma2(ap0, b0, acc2[0][0]);
            acc2[0][1] = fma2(ap0, b1, acc2[0][1]);
            acc2[0][2] = fma2(ap0, b2, acc2[0][2]);
            acc2[0][3] = fma2(ap0, b3, acc2[0][3]);
            acc2[1][0] = fma2(ap1, b0, acc2[1][0]);
            acc2[1][1] = fma2(ap1, b1, acc2[1][1]);
            acc2[1][2] = fma2(ap1, b2, acc2[1][2]);
            acc2[1][3] = fma2(ap1, b3, acc2[1][3]);
            acc2[2][0] = fma2(ap2, b0, acc2[2][0]);
            acc2[2][1] = fma2(ap2, b1, acc2[2][1]);
            acc2[2][2] = fma2(ap2, b2, acc2[2][2]);
            acc2[2][3] = fma2(ap2, b3, acc2[2][3]);
            acc2[3][0] = fma2(ap3, b0, acc2[3][0]);
            acc2[3][1] = fma2(ap3, b1, acc2[3][1]);
            acc2[3][2] = fma2(ap3, b2, acc2[3][2]);
            acc2[3][3] = fma2(ap3, b3, acc2[3][3]);
        }
    }
    #pragma unroll
    for (int i = 0; i < 4; i++) {
        int o = ty * 4 + i;
        float2 u0 = unpack2(acc2[i][0]), u1 = unpack2(acc2[i][1]);
        float2 u2 = unpack2(acc2[i][2]), u3 = unpack2(acc2[i][3]);
        float* dst = g_sraw + ((size_t)b * CC + o) * PS + p0 + tx * 8;
        *(float4*)dst       = make_float4(u0.x, u0.y, u1.x, u1.y);
        *(float4*)(dst + 4) = make_float4(u2.x, u2.y, u3.x, u3.y);
    }

    #pragma unroll
    for (int gg = 0; gg < 2; gg++) {
        float s = 0.f, ss = 0.f;
        #pragma unroll
        for (int i = 2 * gg; i < 2 * gg + 2; i++)
            #pragma unroll
            for (int j = 0; j < 4; j++) {
                float2 u = unpack2(acc2[i][j]);
                s += u.x + u.y; ss += u.x * u.x + u.y * u.y;
            }
        #pragma unroll
        for (int off = 8; off > 0; off >>= 1) {
            s  += __shfl_down_sync(0xffffffffu, s,  off, 16);
            ss += __shfl_down_sync(0xffffffffu, ss, off, 16);
        }
        if (tx == 0)
            g_p0[((size_t)blockIdx.x * 32 + b) * 32 + 2 * ty + gg] = make_float2(s, ss);
    }
}

// ---------------- 3) reduce sgemm partials -> smean/srstd ------------------
__global__ void k_red0() {
    int i = blockIdx.x * 256 + threadIdx.x;
    if (i >= 1024) return;
    int b = i >> 5, g = i & 31;
    float s = 0.f, ss = 0.f;
    #pragma unroll 4
    for (int st = 0; st < 32; st++) {
        float2 v = g_p0[((size_t)st * 32 + b) * 32 + g];
        s += v.x; ss += v.y;
    }
    float m = s * (1.f / 8192.f);
    float var = ss * (1.f / 8192.f) - m * m;
    g_smean[i] = m; g_srstd[i] = rsqrtf(var + 1e-5f);
}

// ---------------- 4) corr = global + 7x7 depthwise local (R1 scalar) -------
__global__ void __launch_bounds__(256) k_corr(const float* __restrict__ gnw,
                                              const float* __restrict__ gnb) {
    int tile = blockIdx.x, c = blockIdx.y, b = blockIdx.z;
    int ty0 = (tile >> 1) * 32, tx0 = (tile & 1) * 32;
    __shared__ float sm[38 * 38];
    __shared__ float kw[49];
    int tid = threadIdx.x;
    int bg = b * NGROUP + (c >> 1);
    float mean = g_smean[bg], rstd = g_srstd[bg];
    float gamma = gnw[c], beta = gnb[c];
    float tg = g_tglob[(size_t)b * CC + c];
    const float* src = g_sraw + ((size_t)b * CC + c) * PS;

    for (int i = tid; i < 38 * 38; i += 256) {
        int yy = i / 38, xx = i - yy * 38;
        int gy = ty0 + yy - 3, gx = tx0 + xx - 3;
        float v = 0.f;
        if ((unsigned)gy < 64u && (unsigned)gx < 64u) {
            float r = src[gy * HS + gx];
            v = fmaxf((r - mean) * rstd * gamma + beta, 0.f);
        }
        sm[i] = v;
    }
    if (tid < 49) kw[tid] = g_tker[((size_t)b * CC + c) * 49 + tid];
    __syncthreads();

    int p = tid * 4;
    int py = p >> 5, px = p & 31;
    float a0 = 0.f, a1 = 0.f, a2 = 0.f, a3 = 0.f;
    #pragma unroll
    for (int ky = 0; ky < 7; ky++) {
        const float* row = &sm[(py + ky) * 38 + px];
        #pragma unroll
        for (int kx = 0; kx < 7; kx++) {
            float w = kw[ky * 7 + kx];
            a0 += w * row[kx];
            a1 += w * row[kx + 1];
            a2 += w * row[kx + 2];
            a3 += w * row[kx + 3];
        }
    }
    const float* ctr = &sm[(py + 3) * 38 + px + 3];
    a0 += tg * ctr[0]; a1 += tg * ctr[1]; a2 += tg * ctr[2]; a3 += tg * ctr[3];

    float* dst = g_corr + ((size_t)b * CC + c) * PS + (ty0 + py) * HS + tx0 + px;
    *(float4*)dst = make_float4(a0, a1, a2, a3);
}

// ---------------- 5) conv3x3 via mma.sync tf32 (tensor pipe) ---------------
// grid (16 tiles of 16x16 px, 32 batch), 512 threads (16 warps).
// Warp w: M-tile m = w&3 (16 oc), N-group ng = w>>2 (64 px = 8 N-tiles of 8).
// K = 64 ci x 9 taps, 8 ci per block-iteration; tap shifts read from halo tile.
__global__ void __launch_bounds__(512) k_conv3(const float* __restrict__ wp1) {
    int tile = blockIdx.x, b = blockIdx.y;
    int ty0 = (tile >> 2) * 16, tx0 = (tile & 3) * 16;
    __shared__ float xs[8][18][20];   // [ci][y][x], stride 20 -> tig banks disjoint
    __shared__ float wsm[9][8][72];   // [tap][ci][oc], stride 72 -> disjoint banks
    int tid = threadIdx.x;
    int w = tid >> 5, lane = tid & 31;
    int gid = lane >> 2, tig = lane & 3;
    int m = w & 3, ng = w >> 2;
    int m0 = m * 16;

    float acc[8][4];
    #pragma unroll
    for (int i = 0; i < 8; i++)
        #pragma unroll
        for (int j = 0; j < 4; j++) acc[i][j] = 0.f;

    for (int cc0 = 0; cc0 < CC; cc0 += 8) {
        __syncthreads();
        for (int i = tid; i < 8 * 324; i += 512) {
            int ci = i / 324; int rem = i - ci * 324;
            int yy = rem / 18, xx = rem - yy * 18;
            int gy = ty0 + yy - 1, gx = tx0 + xx - 1;
            float v = 0.f;
            if ((unsigned)gy < 64u && (unsigned)gx < 64u)
                v = g_corr[((size_t)b * CC + cc0 + ci) * PS + gy * HS + gx];
            xs[ci][yy][xx] = to_tf32(v);
        }
        for (int i = tid; i < 9 * 8 * 64; i += 512) {
            int o = i & 63; int tc = i >> 6;
            int tap = tc >> 3, ci = tc & 7;
            wsm[tap][ci][o] = to_tf32(wp1[o * (CC * 9) + (cc0 + ci) * 9 + tap]);
        }
        __syncthreads();

        #pragma unroll
        for (int tap = 0; tap < 9; tap++) {
            int dy = tap / 3, dx = tap - 3 * (tap / 3);
            unsigned a[4];
            a[0] = __float_as_uint(wsm[tap][tig]    [m0 + gid]);
            a[1] = __float_as_uint(wsm[tap][tig]    [m0 + gid + 8]);
            a[2] = __float_as_uint(wsm[tap][tig + 4][m0 + gid]);
            a[3] = __float_as_uint(wsm[tap][tig + 4][m0 + gid + 8]);
            #pragma unroll
            for (int nt = 0; nt < 8; nt++) {
                int n0 = ng * 64 + nt * 8;
                int y0 = n0 >> 4, x0 = n0 & 15;
                unsigned b0 = __float_as_uint(xs[tig]    [y0 + dy][x0 + gid + dx]);
                unsigned b1 = __float_as_uint(xs[tig + 4][y0 + dy][x0 + gid + dx]);
                mma_tf32(acc[nt], a, b0, b1);
            }
        }
    }

    // store + fused GN stats partials
    float s0 = 0.f, ss0 = 0.f, s1 = 0.f, ss1 = 0.f;
    int oc0 = m0 + gid;
    #pragma unroll
    for (int nt = 0; nt < 8; nt++) {
        int n0 = ng * 64 + nt * 8;
        int y0 = n0 >> 4, x0 = n0 & 15;
        float c0 = acc[nt][0], c1 = acc[nt][1], c2 = acc[nt][2], c3 = acc[nt][3];
        size_t base = (size_t)(ty0 + y0) * HS + tx0 + x0 + 2 * tig;
        *(float2*)(g_y + ((size_t)b * CC + oc0) * PS + base)     = make_float2(c0, c1);
        *(float2*)(g_y + ((size_t)b * CC + oc0 + 8) * PS + base) = make_float2(c2, c3);
        s0 += c0 + c1; ss0 += c0 * c0 + c1 * c1;
        s1 += c2 + c3; ss1 += c2 * c2 + c3 * c3;
    }
    // reduce across the quad (4 lanes sharing gid)
    #pragma unroll
    for (int off = 2; off > 0; off >>= 1) {
        s0  += __shfl_down_sync(0xffffffffu, s0,  off, 4);
        ss0 += __shfl_down_sync(0xffffffffu, ss0, off, 4);
        s1  += __shfl_down_sync(0xffffffffu, s1,  off, 4);
        ss1 += __shfl_down_sync(0xffffffffu, ss1, off, 4);
    }
    if (tig == 0) {
        size_t pbase = ((size_t)tile * 32 + b) * 16 + w;
        g_p1[pbase * 16 + gid]     = make_float2(s0, ss0);
        g_p1[pbase * 16 + gid + 8] = make_float2(s1, ss1);
    }
}

// ---------------- 6) reduce conv3 partials -> pmean/prstd ------------------
__global__ void k_red1() {
    int i = blockIdx.x * 256 + threadIdx.x;
    if (i >= 1024) return;
    int b = i >> 5, g = i & 31;
    float s = 0.f, ss = 0.f;
    #pragma unroll
    for (int cpair = 0; cpair < 2; cpair++) {
        int oc = 2 * g + cpair;
        int m = oc >> 4, rr = oc & 15;
        for (int tile = 0; tile < 16; tile++)
            #pragma unroll
            for (int ngi = 0; ngi < 4; ngi++) {
                int w = ngi * 4 + m;
                float2 v = g_p1[(((size_t)tile * 32 + b) * 16 + w) * 16 + rr];
                s += v.x; ss += v.y;
            }
    }
    float m = s * (1.f / 8192.f);
    float var = ss * (1.f / 8192.f) - m * m;
    g_pmean[i] = m; g_prstd[i] = rsqrtf(var + 1e-5f);
}

// ---------------- 7) final: GN + relu + 1x1 conv to 1 channel (float4) -----
__global__ void k_final(const float* __restrict__ gnw, const float* __restrict__ gnb,
                        const float* __restrict__ w2, const float* __restrict__ b2,
                        float* __restrict__ out) {
    int idx = blockIdx.x * 256 + threadIdx.x;   // 32768 threads, 4 px each
    if (idx >= BATCH * PS / 4) return;
    int b = idx >> 10, p4 = idx & 1023;
    const float4* yb = (const float4*)(g_y + (size_t)b * CC * PS) + p4;
    float bias = b2[0];
    float4 acc = make_float4(bias, bias, bias, bias);
    #pragma unroll 4
    for (int o = 0; o < CC; o++) {
        int bg = b * NGROUP + (o >> 1);
        float m = g_pmean[bg], rs = g_prstd[bg];
        float ga = gnw[o] * rs, be = gnb[o] - m * gnw[o] * rs;
        float wv = w2[o];
        float4 v = yb[(size_t)o * (PS / 4)];
        acc.x += wv * fmaxf(v.x * ga + be, 0.f);
        acc.y += wv * fmaxf(v.y * ga + be, 0.f);
        acc.z += wv * fmaxf(v.z * ga + be, 0.f);
        acc.w += wv * fmaxf(v.w * ga + be, 0.f);
    }
    ((float4*)out)[idx] = acc;
}

// ---------------- launch ----------------------------------------------------
extern "C" void kernel_launch(void* const* d_in, const int* in_sizes, int n_in,
                              void* d_out, int out_size) {
    const float* template_feat = (const float*)d_in[0];
    const float* search_feat   = (const float*)d_in[1];
    const float* w_t    = (const float*)d_in[2];
    const float* gn_t_w = (const float*)d_in[3];
    const float* gn_t_b = (const float*)d_in[4];
    const float* w_s    = (const float*)d_in[5];
    const float* gn_s_w = (const float*)d_in[6];
    const float* gn_s_b = (const float*)d_in[7];
    const float* w_p1   = (const float*)d_in[8];
    const float* gn_p_w = (const float*)d_in[9];
    const float* gn_p_b = (const float*)d_in[10];
    const float* w_p2   = (const float*)d_in[11];
    const float* b_p2   = (const float*)d_in[12];
    float* out = (float*)d_out;

    k_template<<<dim3(BATCH, NGROUP), 128>>>(template_feat, w_t, gn_t_w, gn_t_b);
    k_sgemm<<<dim3(PS / 128, BATCH), 256>>>(search_feat, w_s);
    k_red0<<<4, 256>>>();
    k_corr<<<dim3(4, CC, BATCH), 256>>>(gn_s_w, gn_s_b);
    k_conv3<<<dim3(16, BATCH), 512>>>(w_p1);
    k_red1<<<4, 256>>>();
    k_final<<<128, 256>>>(gn_p_w, gn_p_b, w_p2, b_p2, out);
}

// round 8
// speedup vs baseline: 2.1841x; 1.2238x over previous
#include <cuda_runtime.h>
#include <cuda_bf16.h>

#define BATCH 32
#define CIN   256
#define CC    64
#define PT    196     // 14*14
#define HT    14
#define PS    4096    // 64*64
#define HS    64
#define NGROUP 32     // groups of 2 channels

typedef unsigned long long ull;

// ---------------- packed f32x2 helpers (FFMA2 on sm_103a) -------------------
__device__ __forceinline__ ull fma2(ull a, ull b, ull c) {
    ull d;
    asm("fma.rn.f32x2 %0, %1, %2, %3;" : "=l"(d) : "l"(a), "l"(b), "l"(c));
    return d;
}
__device__ __forceinline__ ull pack2(float lo, float hi) {
    ull d;
    asm("mov.b64 %0, {%1, %2};" : "=l"(d) : "f"(lo), "f"(hi));
    return d;
}
__device__ __forceinline__ float2 unpack2(ull v) {
    float2 r;
    asm("mov.b64 {%0, %1}, %2;" : "=f"(r.x), "=f"(r.y) : "l"(v));
    return r;
}
__device__ __forceinline__ float to_tf32(float v) {
    unsigned u;
    asm("cvt.rna.tf32.f32 %0, %1;" : "=r"(u) : "f"(v));
    return __uint_as_float(u);
}
__device__ __forceinline__ void mma_tf32(float* c, const unsigned* a,
                                         unsigned b0, unsigned b1) {
    asm("mma.sync.aligned.m16n8k8.row.col.f32.tf32.tf32.f32 "
        "{%0,%1,%2,%3}, {%4,%5,%6,%7}, {%8,%9}, {%0,%1,%2,%3};"
        : "+f"(c[0]), "+f"(c[1]), "+f"(c[2]), "+f"(c[3])
        : "r"(a[0]), "r"(a[1]), "r"(a[2]), "r"(a[3]), "r"(b0), "r"(b1));
}

// ---------------- scratch (device globals; allocation-free) ----------------
__device__ float g_sraw[(size_t)BATCH*CC*PS];   // raw search conv1x1 (pre-GN)
__device__ float g_corr[(size_t)BATCH*CC*PS];   // global+local correlation
__device__ float g_y   [(size_t)BATCH*CC*PS];   // conv3x3 output (pre-GN)
__device__ float g_tker[(size_t)BATCH*CC*49];   // pooled 7x7 template kernels
__device__ float g_tglob[(size_t)BATCH*CC];     // template global means
__device__ float g_smean[BATCH*NGROUP];
__device__ float g_srstd[BATCH*NGROUP];
__device__ float g_pmean[BATCH*NGROUP];
__device__ float g_prstd[BATCH*NGROUP];
__device__ float2 g_p0[512*16*16];              // sgemm stats partials
__device__ float2 g_p1[512*16*16];              // conv3 stats partials

// ---------------- 1) template branch: conv1x1 + GN + relu + pools ----------
__global__ void k_template(const float* __restrict__ tf, const float* __restrict__ wt,
                           const float* __restrict__ gw, const float* __restrict__ gb) {
    int b = blockIdx.x, g = blockIdx.y;
    __shared__ float tv[392];
    __shared__ ull  wsm[256];            // (w[2g][ci], w[2g+1][ci])
    __shared__ float r1[128], r2[128];
    __shared__ float s_mean, s_rstd;
    int tid = threadIdx.x;
    const float* x = tf + (size_t)b * CIN * PT;

    for (int i = tid; i < 256; i += 128)
        wsm[i] = pack2(wt[(g * 2) * CIN + i], wt[(g * 2 + 1) * CIN + i]);
    __syncthreads();

    for (int p = tid; p < PT; p += 128) {
        ull acc = 0ull;
        #pragma unroll 4
        for (int ci = 0; ci < CIN; ci++) {
            float xv = x[ci * PT + p];
            acc = fma2(wsm[ci], pack2(xv, xv), acc);
        }
        float2 r = unpack2(acc);
        tv[p] = r.x; tv[PT + p] = r.y;
    }
    __syncthreads();

    float s = 0.f, ss = 0.f;
    for (int idx = tid; idx < 392; idx += 128) { float v = tv[idx]; s += v; ss += v * v; }
    r1[tid] = s; r2[tid] = ss;
    __syncthreads();
    for (int o = 64; o > 0; o >>= 1) {
        if (tid < o) { r1[tid] += r1[tid + o]; r2[tid] += r2[tid + o]; }
        __syncthreads();
    }
    if (tid == 0) {
        float m = r1[0] * (1.f / 392.f);
        float var = r2[0] * (1.f / 392.f) - m * m;
        s_mean = m; s_rstd = rsqrtf(var + 1e-5f);
    }
    __syncthreads();

    for (int idx = tid; idx < 392; idx += 128) {
        int c = idx / PT;
        float v = (tv[idx] - s_mean) * s_rstd * gw[g * 2 + c] + gb[g * 2 + c];
        tv[idx] = fmaxf(v, 0.f);
    }
    __syncthreads();

    if (tid < 98) {
        int c = tid / 49, cell = tid - c * 49;
        int i = cell / 7, j = cell - i * 7;
        int base = c * PT + (2 * i) * HT + 2 * j;
        float v = 0.25f * (tv[base] + tv[base + 1] + tv[base + HT] + tv[base + HT + 1]);
        g_tker[((size_t)b * CC + g * 2 + c) * 49 + cell] = v;
    }
    if (tid < 2) {
        float acc = 0.f;
        for (int p = 0; p < PT; p++) acc += tv[tid * PT + p];
        g_tglob[(size_t)b * CC + g * 2 + tid] = acc * (1.f / 196.f);
    }
}

// ---------------- 2) search conv1x1 GEMM via mma.sync tf32 -----------------
// grid (16 strips of 256 px, 32 batch), 512 threads (16 warps).
// Warp w: m = w&3 (16 oc), ng = w>>2 (64 px = 8 N-tiles of 8). K=256, 16/iter.
__global__ void __launch_bounds__(512) k_sgemm(const float* __restrict__ sf,
                                               const float* __restrict__ ws) {
    int strip = blockIdx.x, b = blockIdx.y;
    int p0 = strip * 256;
    __shared__ float As[16][72];    // [k][oc], stride 72 -> conflict-free frags
    __shared__ float Bs[16][264];   // [k][px], stride 264 -> conflict-free frags
    int tid = threadIdx.x;
    int w = tid >> 5, lane = tid & 31;
    int gid = lane >> 2, tig = lane & 3;
    int m = w & 3, ng = w >> 2;
    int m0 = m * 16;

    float acc[8][4];
    #pragma unroll
    for (int i = 0; i < 8; i++)
        #pragma unroll
        for (int j = 0; j < 4; j++) acc[i][j] = 0.f;

    const float* xb = sf + (size_t)b * CIN * PS + p0;

    for (int k0 = 0; k0 < CIN; k0 += 16) {
        __syncthreads();
        for (int i = tid; i < 1024; i += 512) {
            int o = i >> 4, k = i & 15;
            As[k][o] = to_tf32(ws[o * CIN + k0 + k]);
        }
        for (int i = tid; i < 1024; i += 512) {
            int k = i >> 6, p4 = i & 63;
            float4 v = ((const float4*)(xb + (size_t)(k0 + k) * PS))[p4];
            v.x = to_tf32(v.x); v.y = to_tf32(v.y);
            v.z = to_tf32(v.z); v.w = to_tf32(v.w);
            ((float4*)&Bs[k][0])[p4] = v;
        }
        __syncthreads();

        #pragma unroll
        for (int ks = 0; ks < 2; ks++) {
            int kb = 8 * ks;
            unsigned a[4];
            a[0] = __float_as_uint(As[kb + tig]    [m0 + gid]);
            a[1] = __float_as_uint(As[kb + tig]    [m0 + gid + 8]);
            a[2] = __float_as_uint(As[kb + tig + 4][m0 + gid]);
            a[3] = __float_as_uint(As[kb + tig + 4][m0 + gid + 8]);
            #pragma unroll
            for (int nt = 0; nt < 8; nt++) {
                int n0 = ng * 64 + nt * 8;
                unsigned b0 = __float_as_uint(Bs[kb + tig]    [n0 + gid]);
                unsigned b1 = __float_as_uint(Bs[kb + tig + 4][n0 + gid]);
                mma_tf32(acc[nt], a, b0, b1);
            }
        }
    }

    // store + fused GN stats partials
    float s0 = 0.f, ss0 = 0.f, s1 = 0.f, ss1 = 0.f;
    int oc0 = m0 + gid;
    #pragma unroll
    for (int nt = 0; nt < 8; nt++) {
        int n0 = ng * 64 + nt * 8;
        float c0 = acc[nt][0], c1 = acc[nt][1], c2 = acc[nt][2], c3 = acc[nt][3];
        size_t base = (size_t)p0 + n0 + 2 * tig;
        *(float2*)(g_sraw + ((size_t)b * CC + oc0) * PS + base)     = make_float2(c0, c1);
        *(float2*)(g_sraw + ((size_t)b * CC + oc0 + 8) * PS + base) = make_float2(c2, c3);
        s0 += c0 + c1; ss0 += c0 * c0 + c1 * c1;
        s1 += c2 + c3; ss1 += c2 * c2 + c3 * c3;
    }
    #pragma unroll
    for (int off = 2; off > 0; off >>= 1) {
        s0  += __shfl_down_sync(0xffffffffu, s0,  off, 4);
        ss0 += __shfl_down_sync(0xffffffffu, ss0, off, 4);
        s1  += __shfl_down_sync(0xffffffffu, s1,  off, 4);
        ss1 += __shfl_down_sync(0xffffffffu, ss1, off, 4);
    }
    if (tig == 0) {
        size_t pbase = ((size_t)strip * 32 + b) * 16 + w;
        g_p0[pbase * 16 + gid]     = make_float2(s0, ss0);
        g_p0[pbase * 16 + gid + 8] = make_float2(s1, ss1);
    }
}

// ---------------- 3) reduce partials -> mean/rstd (shared by both GNs) -----
__global__ void k_red(int which) {
    int i = blockIdx.x * 256 + threadIdx.x;
    if (i >= 1024) return;
    const float2* part = which ? g_p1 : g_p0;
    float* mean = which ? g_pmean : g_smean;
    float* rstd = which ? g_prstd : g_srstd;
    int b = i >> 5, g = i & 31;
    float s = 0.f, ss = 0.f;
    #pragma unroll
    for (int cpair = 0; cpair < 2; cpair++) {
        int oc = 2 * g + cpair;
        int m = oc >> 4, rr = oc & 15;
        for (int tile = 0; tile < 16; tile++)
            #pragma unroll
            for (int ngi = 0; ngi < 4; ngi++) {
                int w = ngi * 4 + m;
                float2 v = part[(((size_t)tile * 32 + b) * 16 + w) * 16 + rr];
                s += v.x; ss += v.y;
            }
    }
    float m = s * (1.f / 8192.f);
    float var = ss * (1.f / 8192.f) - m * m;
    mean[i] = m; rstd[i] = rsqrtf(var + 1e-5f);
}

// ---------------- 4) corr = global + 7x7 depthwise local (R1 scalar) -------
__global__ void __launch_bounds__(256) k_corr(const float* __restrict__ gnw,
                                              const float* __restrict__ gnb) {
    int tile = blockIdx.x, c = blockIdx.y, b = blockIdx.z;
    int ty0 = (tile >> 1) * 32, tx0 = (tile & 1) * 32;
    __shared__ float sm[38 * 38];
    __shared__ float kw[49];
    int tid = threadIdx.x;
    int bg = b * NGROUP + (c >> 1);
    float mean = g_smean[bg], rstd = g_srstd[bg];
    float gamma = gnw[c], beta = gnb[c];
    float tg = g_tglob[(size_t)b * CC + c];
    const float* src = g_sraw + ((size_t)b * CC + c) * PS;

    for (int i = tid; i < 38 * 38; i += 256) {
        int yy = i / 38, xx = i - yy * 38;
        int gy = ty0 + yy - 3, gx = tx0 + xx - 3;
        float v = 0.f;
        if ((unsigned)gy < 64u && (unsigned)gx < 64u) {
            float r = src[gy * HS + gx];
            v = fmaxf((r - mean) * rstd * gamma + beta, 0.f);
        }
        sm[i] = v;
    }
    if (tid < 49) kw[tid] = g_tker[((size_t)b * CC + c) * 49 + tid];
    __syncthreads();

    int p = tid * 4;
    int py = p >> 5, px = p & 31;
    float a0 = 0.f, a1 = 0.f, a2 = 0.f, a3 = 0.f;
    #pragma unroll
    for (int ky = 0; ky < 7; ky++) {
        const float* row = &sm[(py + ky) * 38 + px];
        #pragma unroll
        for (int kx = 0; kx < 7; kx++) {
            float w = kw[ky * 7 + kx];
            a0 += w * row[kx];
            a1 += w * row[kx + 1];
            a2 += w * row[kx + 2];
            a3 += w * row[kx + 3];
        }
    }
    const float* ctr = &sm[(py + 3) * 38 + px + 3];
    a0 += tg * ctr[0]; a1 += tg * ctr[1]; a2 += tg * ctr[2]; a3 += tg * ctr[3];

    float* dst = g_corr + ((size_t)b * CC + c) * PS + (ty0 + py) * HS + tx0 + px;
    *(float4*)dst = make_float4(a0, a1, a2, a3);
}

// ---------------- 5) conv3x3 via mma.sync tf32 (tensor pipe) ---------------
__global__ void __launch_bounds__(512) k_conv3(const float* __restrict__ wp1) {
    int tile = blockIdx.x, b = blockIdx.y;
    int ty0 = (tile >> 2) * 16, tx0 = (tile & 3) * 16;
    __shared__ float xs[8][18][20];
    __shared__ float wsm[9][8][72];
    int tid = threadIdx.x;
    int w = tid >> 5, lane = tid & 31;
    int gid = lane >> 2, tig = lane & 3;
    int m = w & 3, ng = w >> 2;
    int m0 = m * 16;

    float acc[8][4];
    #pragma unroll
    for (int i = 0; i < 8; i++)
        #pragma unroll
        for (int j = 0; j < 4; j++) acc[i][j] = 0.f;

    for (int cc0 = 0; cc0 < CC; cc0 += 8) {
        __syncthreads();
        for (int i = tid; i < 8 * 324; i += 512) {
            int ci = i / 324; int rem = i - ci * 324;
            int yy = rem / 18, xx = rem - yy * 18;
            int gy = ty0 + yy - 1, gx = tx0 + xx - 1;
            float v = 0.f;
            if ((unsigned)gy < 64u && (unsigned)gx < 64u)
                v = g_corr[((size_t)b * CC + cc0 + ci) * PS + gy * HS + gx];
            xs[ci][yy][xx] = to_tf32(v);
        }
        for (int i = tid; i < 9 * 8 * 64; i += 512) {
            int o = i & 63; int tc = i >> 6;
            int tap = tc >> 3, ci = tc & 7;
            wsm[tap][ci][o] = to_tf32(wp1[o * (CC * 9) + (cc0 + ci) * 9 + tap]);
        }
        __syncthreads();

        #pragma unroll
        for (int tap = 0; tap < 9; tap++) {
            int dy = tap / 3, dx = tap - 3 * (tap / 3);
            unsigned a[4];
            a[0] = __float_as_uint(wsm[tap][tig]    [m0 + gid]);
            a[1] = __float_as_uint(wsm[tap][tig]    [m0 + gid + 8]);
            a[2] = __float_as_uint(wsm[tap][tig + 4][m0 + gid]);
            a[3] = __float_as_uint(wsm[tap][tig + 4][m0 + gid + 8]);
            #pragma unroll
            for (int nt = 0; nt < 8; nt++) {
                int n0 = ng * 64 + nt * 8;
                int y0 = n0 >> 4, x0 = n0 & 15;
                unsigned b0 = __float_as_uint(xs[tig]    [y0 + dy][x0 + gid + dx]);
                unsigned b1 = __float_as_uint(xs[tig + 4][y0 + dy][x0 + gid + dx]);
                mma_tf32(acc[nt], a, b0, b1);
            }
        }
    }

    float s0 = 0.f, ss0 = 0.f, s1 = 0.f, ss1 = 0.f;
    int oc0 = m0 + gid;
    #pragma unroll
    for (int nt = 0; nt < 8; nt++) {
        int n0 = ng * 64 + nt * 8;
        int y0 = n0 >> 4, x0 = n0 & 15;
        float c0 = acc[nt][0], c1 = acc[nt][1], c2 = acc[nt][2], c3 = acc[nt][3];
        size_t base = (size_t)(ty0 + y0) * HS + tx0 + x0 + 2 * tig;
        *(float2*)(g_y + ((size_t)b * CC + oc0) * PS + base)     = make_float2(c0, c1);
        *(float2*)(g_y + ((size_t)b * CC + oc0 + 8) * PS + base) = make_float2(c2, c3);
        s0 += c0 + c1; ss0 += c0 * c0 + c1 * c1;
        s1 += c2 + c3; ss1 += c2 * c2 + c3 * c3;
    }
    #pragma unroll
    for (int off = 2; off > 0; off >>= 1) {
        s0  += __shfl_down_sync(0xffffffffu, s0,  off, 4);
        ss0 += __shfl_down_sync(0xffffffffu, ss0, off, 4);
        s1  += __shfl_down_sync(0xffffffffu, s1,  off, 4);
        ss1 += __shfl_down_sync(0xffffffffu, ss1, off, 4);
    }
    if (tig == 0) {
        size_t pbase = ((size_t)tile * 32 + b) * 16 + w;
        g_p1[pbase * 16 + gid]     = make_float2(s0, ss0);
        g_p1[pbase * 16 + gid + 8] = make_float2(s1, ss1);
    }
}

// ---------------- 7) final: GN + relu + 1x1 conv to 1 channel (float4) -----
__global__ void k_final(const float* __restrict__ gnw, const float* __restrict__ gnb,
                        const float* __restrict__ w2, const float* __restrict__ b2,
                        float* __restrict__ out) {
    int idx = blockIdx.x * 256 + threadIdx.x;   // 32768 threads, 4 px each
    if (idx >= BATCH * PS / 4) return;
    int b = idx >> 10, p4 = idx & 1023;
    const float4* yb = (const float4*)(g_y + (size_t)b * CC * PS) + p4;
    float bias = b2[0];
    float4 acc = make_float4(bias, bias, bias, bias);
    #pragma unroll 4
    for (int o = 0; o < CC; o++) {
        int bg = b * NGROUP + (o >> 1);
        float m = g_pmean[bg], rs = g_prstd[bg];
        float ga = gnw[o] * rs, be = gnb[o] - m * gnw[o] * rs;
        float wv = w2[o];
        float4 v = yb[(size_t)o * (PS / 4)];
        acc.x += wv * fmaxf(v.x * ga + be, 0.f);
        acc.y += wv * fmaxf(v.y * ga + be, 0.f);
        acc.z += wv * fmaxf(v.z * ga + be, 0.f);
        acc.w += wv * fmaxf(v.w * ga + be, 0.f);
    }
    ((float4*)out)[idx] = acc;
}

// ---------------- launch ----------------------------------------------------
extern "C" void kernel_launch(void* const* d_in, const int* in_sizes, int n_in,
                              void* d_out, int out_size) {
    const float* template_feat = (const float*)d_in[0];
    const float* search_feat   = (const float*)d_in[1];
    const float* w_t    = (const float*)d_in[2];
    const float* gn_t_w = (const float*)d_in[3];
    const float* gn_t_b = (const float*)d_in[4];
    const float* w_s    = (const float*)d_in[5];
    const float* gn_s_w = (const float*)d_in[6];
    const float* gn_s_b = (const float*)d_in[7];
    const float* w_p1   = (const float*)d_in[8];
    const float* gn_p_w = (const float*)d_in[9];
    const float* gn_p_b = (const float*)d_in[10];
    const float* w_p2   = (const float*)d_in[11];
    const float* b_p2   = (const float*)d_in[12];
    float* out = (float*)d_out;

    k_template<<<dim3(BATCH, NGROUP), 128>>>(template_feat, w_t, gn_t_w, gn_t_b);
    k_sgemm<<<dim3(16, BATCH), 512>>>(search_feat, w_s);
    k_red<<<4, 256>>>(0);
    k_corr<<<dim3(4, CC, BATCH), 256>>>(gn_s_w, gn_s_b);
    k_conv3<<<dim3(16, BATCH), 512>>>(w_p1);
    k_red<<<4, 256>>>(1);
    k_final<<<128, 256>>>(gn_p_w, gn_p_b, w_p2, b_p2, out);
}

// round 10
// speedup vs baseline: 2.5653x; 1.1745x over previous
#include <cuda_runtime.h>
#include <cuda_bf16.h>

#define BATCH 32
#define CIN   256
#define CC    64
#define PT    196     // 14*14
#define HT    14
#define PS    4096    // 64*64
#define HS    64
#define NGROUP 32     // groups of 2 channels

typedef unsigned long long ull;

// ---------------- packed f32x2 / tf32 helpers -------------------------------
__device__ __forceinline__ ull fma2(ull a, ull b, ull c) {
    ull d;
    asm("fma.rn.f32x2 %0, %1, %2, %3;" : "=l"(d) : "l"(a), "l"(b), "l"(c));
    return d;
}
__device__ __forceinline__ ull pack2(float lo, float hi) {
    ull d;
    asm("mov.b64 %0, {%1, %2};" : "=l"(d) : "f"(lo), "f"(hi));
    return d;
}
__device__ __forceinline__ float2 unpack2(ull v) {
    float2 r;
    asm("mov.b64 {%0, %1}, %2;" : "=f"(r.x), "=f"(r.y) : "l"(v));
    return r;
}
__device__ __forceinline__ float to_tf32(float v) {
    unsigned u;
    asm("cvt.rna.tf32.f32 %0, %1;" : "=r"(u) : "f"(v));
    return __uint_as_float(u);
}
__device__ __forceinline__ void mma_tf32(float* c, const unsigned* a,
                                         unsigned b0, unsigned b1) {
    asm("mma.sync.aligned.m16n8k8.row.col.f32.tf32.tf32.f32 "
        "{%0,%1,%2,%3}, {%4,%5,%6,%7}, {%8,%9}, {%0,%1,%2,%3};"
        : "+f"(c[0]), "+f"(c[1]), "+f"(c[2]), "+f"(c[3])
        : "r"(a[0]), "r"(a[1]), "r"(a[2]), "r"(a[3]), "r"(b0), "r"(b1));
}

// ---------------- scratch (device globals; allocation-free) ----------------
__device__ float g_sraw[(size_t)BATCH*CC*PS];   // raw search conv1x1 (pre-GN)
__device__ float g_corr[(size_t)BATCH*CC*PS];   // global+local correlation
__device__ float g_y   [(size_t)BATCH*CC*PS];   // conv3x3 output (pre-GN)
__device__ float g_tker[(size_t)BATCH*CC*49];   // pooled 7x7 template kernels
__device__ float g_tglob[(size_t)BATCH*CC];     // template global means
__device__ float g_smean[BATCH*NGROUP];
__device__ float g_srstd[BATCH*NGROUP];
__device__ float g_pmean[BATCH*NGROUP];
__device__ float g_prstd[BATCH*NGROUP];
__device__ float2 g_p0[512*16*16];              // sgemm stats partials
__device__ float2 g_p1[256*32*16];              // conv3 stats partials

// ---------------- 1) template branch: conv1x1 + GN + relu + pools ----------
__global__ void k_template(const float* __restrict__ tf, const float* __restrict__ wt,
                           const float* __restrict__ gw, const float* __restrict__ gb) {
    int b = blockIdx.x, g = blockIdx.y;
    __shared__ float tv[392];
    __shared__ ull  wsm[256];            // (w[2g][ci], w[2g+1][ci])
    __shared__ float r1[128], r2[128];
    __shared__ float s_mean, s_rstd;
    int tid = threadIdx.x;
    const float* x = tf + (size_t)b * CIN * PT;

    for (int i = tid; i < 256; i += 128)
        wsm[i] = pack2(wt[(g * 2) * CIN + i], wt[(g * 2 + 1) * CIN + i]);
    __syncthreads();

    for (int p = tid; p < PT; p += 128) {
        ull acc = 0ull;
        #pragma unroll 4
        for (int ci = 0; ci < CIN; ci++) {
            float xv = x[ci * PT + p];
            acc = fma2(wsm[ci], pack2(xv, xv), acc);
        }
        float2 r = unpack2(acc);
        tv[p] = r.x; tv[PT + p] = r.y;
    }
    __syncthreads();

    float s = 0.f, ss = 0.f;
    for (int idx = tid; idx < 392; idx += 128) { float v = tv[idx]; s += v; ss += v * v; }
    r1[tid] = s; r2[tid] = ss;
    __syncthreads();
    for (int o = 64; o > 0; o >>= 1) {
        if (tid < o) { r1[tid] += r1[tid + o]; r2[tid] += r2[tid + o]; }
        __syncthreads();
    }
    if (tid == 0) {
        float m = r1[0] * (1.f / 392.f);
        float var = r2[0] * (1.f / 392.f) - m * m;
        s_mean = m; s_rstd = rsqrtf(var + 1e-5f);
    }
    __syncthreads();

    for (int idx = tid; idx < 392; idx += 128) {
        int c = idx / PT;
        float v = (tv[idx] - s_mean) * s_rstd * gw[g * 2 + c] + gb[g * 2 + c];
        tv[idx] = fmaxf(v, 0.f);
    }
    __syncthreads();

    if (tid < 98) {
        int c = tid / 49, cell = tid - c * 49;
        int i = cell / 7, j = cell - i * 7;
        int base = c * PT + (2 * i) * HT + 2 * j;
        float v = 0.25f * (tv[base] + tv[base + 1] + tv[base + HT] + tv[base + HT + 1]);
        g_tker[((size_t)b * CC + g * 2 + c) * 49 + cell] = v;
    }
    if (tid < 2) {
        float acc = 0.f;
        for (int p = 0; p < PT; p++) acc += tv[tid * PT + p];
        g_tglob[(size_t)b * CC + g * 2 + tid] = acc * (1.f / 196.f);
    }
}

// ---------------- 2) search conv1x1 GEMM via mma.sync tf32 -----------------
// grid (16 strips of 256 px, 32 batch), 512 threads (16 warps).
__global__ void __launch_bounds__(512) k_sgemm(const float* __restrict__ sf,
                                               const float* __restrict__ ws) {
    int strip = blockIdx.x, b = blockIdx.y;
    int p0 = strip * 256;
    __shared__ float As[16][72];    // [k][oc], stride 72 -> conflict-free frags
    __shared__ float Bs[16][264];   // [k][px], stride 264 -> conflict-free frags
    int tid = threadIdx.x;
    int w = tid >> 5, lane = tid & 31;
    int gid = lane >> 2, tig = lane & 3;
    int m = w & 3, ng = w >> 2;
    int m0 = m * 16;

    float acc[8][4];
    #pragma unroll
    for (int i = 0; i < 8; i++)
        #pragma unroll
        for (int j = 0; j < 4; j++) acc[i][j] = 0.f;

    const float* xb = sf + (size_t)b * CIN * PS + p0;

    for (int k0 = 0; k0 < CIN; k0 += 16) {
        __syncthreads();
        for (int i = tid; i < 1024; i += 512) {
            int o = i >> 4, k = i & 15;
            As[k][o] = to_tf32(ws[o * CIN + k0 + k]);
        }
        for (int i = tid; i < 1024; i += 512) {
            int k = i >> 6, p4 = i & 63;
            float4 v = ((const float4*)(xb + (size_t)(k0 + k) * PS))[p4];
            v.x = to_tf32(v.x); v.y = to_tf32(v.y);
            v.z = to_tf32(v.z); v.w = to_tf32(v.w);
            ((float4*)&Bs[k][0])[p4] = v;
        }
        __syncthreads();

        #pragma unroll
        for (int ks = 0; ks < 2; ks++) {
            int kb = 8 * ks;
            unsigned a[4];
            a[0] = __float_as_uint(As[kb + tig]    [m0 + gid]);
            a[1] = __float_as_uint(As[kb + tig]    [m0 + gid + 8]);
            a[2] = __float_as_uint(As[kb + tig + 4][m0 + gid]);
            a[3] = __float_as_uint(As[kb + tig + 4][m0 + gid + 8]);
            #pragma unroll
            for (int nt = 0; nt < 8; nt++) {
                int n0 = ng * 64 + nt * 8;
                unsigned b0 = __float_as_uint(Bs[kb + tig]    [n0 + gid]);
                unsigned b1 = __float_as_uint(Bs[kb + tig + 4][n0 + gid]);
                mma_tf32(acc[nt], a, b0, b1);
            }
        }
    }

    float s0 = 0.f, ss0 = 0.f, s1 = 0.f, ss1 = 0.f;
    int oc0 = m0 + gid;
    #pragma unroll
    for (int nt = 0; nt < 8; nt++) {
        int n0 = ng * 64 + nt * 8;
        float c0 = acc[nt][0], c1 = acc[nt][1], c2 = acc[nt][2], c3 = acc[nt][3];
        size_t base = (size_t)p0 + n0 + 2 * tig;
        *(float2*)(g_sraw + ((size_t)b * CC + oc0) * PS + base)     = make_float2(c0, c1);
        *(float2*)(g_sraw + ((size_t)b * CC + oc0 + 8) * PS + base) = make_float2(c2, c3);
        s0 += c0 + c1; ss0 += c0 * c0 + c1 * c1;
        s1 += c2 + c3; ss1 += c2 * c2 + c3 * c3;
    }
    #pragma unroll
    for (int off = 2; off > 0; off >>= 1) {
        s0  += __shfl_down_sync(0xffffffffu, s0,  off, 4);
        ss0 += __shfl_down_sync(0xffffffffu, ss0, off, 4);
        s1  += __shfl_down_sync(0xffffffffu, s1,  off, 4);
        ss1 += __shfl_down_sync(0xffffffffu, ss1, off, 4);
    }
    if (tig == 0) {
        size_t pbase = ((size_t)strip * 32 + b) * 16 + w;
        g_p0[pbase * 16 + gid]     = make_float2(s0, ss0);
        g_p0[pbase * 16 + gid + 8] = make_float2(s1, ss1);
    }
}

// ---------------- 3) reduce sgemm partials -> smean/srstd ------------------
__global__ void k_red0() {
    int i = blockIdx.x * 256 + threadIdx.x;
    if (i >= 1024) return;
    int b = i >> 5, g = i & 31;
    float s = 0.f, ss = 0.f;
    #pragma unroll
    for (int cpair = 0; cpair < 2; cpair++) {
        int oc = 2 * g + cpair;
        int m = oc >> 4, rr = oc & 15;
        for (int tile = 0; tile < 16; tile++)
            #pragma unroll
            for (int ngi = 0; ngi < 4; ngi++) {
                int w = ngi * 4 + m;
                float2 v = g_p0[(((size_t)tile * 32 + b) * 16 + w) * 16 + rr];
                s += v.x; ss += v.y;
            }
    }
    float m = s * (1.f / 8192.f);
    float var = ss * (1.f / 8192.f) - m * m;
    g_smean[i] = m; g_srstd[i] = rsqrtf(var + 1e-5f);
}

// ---------------- 4) corr = global + 7x7 depthwise local (R1 scalar) -------
__global__ void __launch_bounds__(256) k_corr(const float* __restrict__ gnw,
                                              const float* __restrict__ gnb) {
    int tile = blockIdx.x, c = blockIdx.y, b = blockIdx.z;
    int ty0 = (tile >> 1) * 32, tx0 = (tile & 1) * 32;
    __shared__ float sm[38 * 38];
    __shared__ float kw[49];
    int tid = threadIdx.x;
    int bg = b * NGROUP + (c >> 1);
    float mean = g_smean[bg], rstd = g_srstd[bg];
    float gamma = gnw[c], beta = gnb[c];
    float tg = g_tglob[(size_t)b * CC + c];
    const float* src = g_sraw + ((size_t)b * CC + c) * PS;

    for (int i = tid; i < 38 * 38; i += 256) {
        int yy = i / 38, xx = i - yy * 38;
        int gy = ty0 + yy - 3, gx = tx0 + xx - 3;
        float v = 0.f;
        if ((unsigned)gy < 64u && (unsigned)gx < 64u) {
            float r = src[gy * HS + gx];
            v = fmaxf((r - mean) * rstd * gamma + beta, 0.f);
        }
        sm[i] = v;
    }
    if (tid < 49) kw[tid] = g_tker[((size_t)b * CC + c) * 49 + tid];
    __syncthreads();

    int p = tid * 4;
    int py = p >> 5, px = p & 31;
    float a0 = 0.f, a1 = 0.f, a2 = 0.f, a3 = 0.f;
    #pragma unroll
    for (int ky = 0; ky < 7; ky++) {
        const float* row = &sm[(py + ky) * 38 + px];
        #pragma unroll
        for (int kx = 0; kx < 7; kx++) {
            float w = kw[ky * 7 + kx];
            a0 += w * row[kx];
            a1 += w * row[kx + 1];
            a2 += w * row[kx + 2];
            a3 += w * row[kx + 3];
        }
    }
    const float* ctr = &sm[(py + 3) * 38 + px + 3];
    a0 += tg * ctr[0]; a1 += tg * ctr[1]; a2 += tg * ctr[2]; a3 += tg * ctr[3];

    float* dst = g_corr + ((size_t)b * CC + c) * PS + (ty0 + py) * HS + tx0 + px;
    *(float4*)dst = make_float4(a0, a1, a2, a3);
}

// ---------------- 5) conv3x3 via mma.sync tf32, 16x32 px tile --------------
// grid (8 tiles, 32 batch), 1024 threads (32 warps).
// Warp w: m = w&3 (16 oc), ng = w>>2 (0..7 -> 64 px each of the 512-px tile).
__global__ void __launch_bounds__(1024) k_conv3(const float* __restrict__ wp1) {
    int tile = blockIdx.x, b = blockIdx.y;
    int ty0 = (tile >> 1) * 16, tx0 = (tile & 1) * 32;
    __shared__ float xs[8][18][36];   // [ci][y][x]; ci-stride 648 = 8 mod 32
    __shared__ float wsm[9][8][72];   // [tap][ci][oc]; ci-stride 72 = 8 mod 32
    int tid = threadIdx.x;
    int w = tid >> 5, lane = tid & 31;
    int gid = lane >> 2, tig = lane & 3;
    int m = w & 3, ng = w >> 2;
    int m0 = m * 16;

    float acc[8][4];
    #pragma unroll
    for (int i = 0; i < 8; i++)
        #pragma unroll
        for (int j = 0; j < 4; j++) acc[i][j] = 0.f;

    for (int cc0 = 0; cc0 < CC; cc0 += 8) {
        __syncthreads();
        // x tile: 8 ci x 18 rows x 34 cols (halo +-1)
        for (int i = tid; i < 8 * 612; i += 1024) {
            int ci = i / 612; int rem = i - ci * 612;
            int yy = rem / 34, xx = rem - yy * 34;
            int gy = ty0 + yy - 1, gx = tx0 + xx - 1;
            float v = 0.f;
            if ((unsigned)gy < 64u && (unsigned)gx < 64u)
                v = g_corr[((size_t)b * CC + cc0 + ci) * PS + gy * HS + gx];
            xs[ci][yy][xx] = to_tf32(v);
        }
        for (int i = tid; i < 9 * 8 * 64; i += 1024) {
            int o = i & 63; int tc = i >> 6;
            int tap = tc >> 3, ci = tc & 7;
            wsm[tap][ci][o] = to_tf32(wp1[o * (CC * 9) + (cc0 + ci) * 9 + tap]);
        }
        __syncthreads();

        #pragma unroll
        for (int tap = 0; tap < 9; tap++) {
            int dy = tap / 3, dx = tap - 3 * (tap / 3);
            unsigned a[4];
            a[0] = __float_as_uint(wsm[tap][tig]    [m0 + gid]);
            a[1] = __float_as_uint(wsm[tap][tig]    [m0 + gid + 8]);
            a[2] = __float_as_uint(wsm[tap][tig + 4][m0 + gid]);
            a[3] = __float_as_uint(wsm[tap][tig + 4][m0 + gid + 8]);
            #pragma unroll
            for (int nt = 0; nt < 8; nt++) {
                int n0 = ng * 64 + nt * 8;
                int y0 = n0 >> 5, x0 = n0 & 31;
                unsigned b0 = __float_as_uint(xs[tig]    [y0 + dy][x0 + gid + dx]);
                unsigned b1 = __float_as_uint(xs[tig + 4][y0 + dy][x0 + gid + dx]);
                mma_tf32(acc[nt], a, b0, b1);
            }
        }
    }

    // store fp32 + fused GN stats partials
    float s0 = 0.f, ss0 = 0.f, s1 = 0.f, ss1 = 0.f;
    int oc0 = m0 + gid;
    #pragma unroll
    for (int nt = 0; nt < 8; nt++) {
        int n0 = ng * 64 + nt * 8;
        int y0 = n0 >> 5, x0 = n0 & 31;
        float c0 = acc[nt][0], c1 = acc[nt][1], c2 = acc[nt][2], c3 = acc[nt][3];
        size_t base = (size_t)(ty0 + y0) * HS + tx0 + x0 + 2 * tig;
        *(float2*)(g_y + ((size_t)b * CC + oc0) * PS + base)     = make_float2(c0, c1);
        *(float2*)(g_y + ((size_t)b * CC + oc0 + 8) * PS + base) = make_float2(c2, c3);
        s0 += c0 + c1; ss0 += c0 * c0 + c1 * c1;
        s1 += c2 + c3; ss1 += c2 * c2 + c3 * c3;
    }
    #pragma unroll
    for (int off = 2; off > 0; off >>= 1) {
        s0  += __shfl_down_sync(0xffffffffu, s0,  off, 4);
        ss0 += __shfl_down_sync(0xffffffffu, ss0, off, 4);
        s1  += __shfl_down_sync(0xffffffffu, s1,  off, 4);
        ss1 += __shfl_down_sync(0xffffffffu, ss1, off, 4);
    }
    if (tig == 0) {
        size_t pbase = ((size_t)tile * 32 + b) * 32 + w;
        g_p1[pbase * 16 + gid]     = make_float2(s0, ss0);
        g_p1[pbase * 16 + gid + 8] = make_float2(s1, ss1);
    }
}

// ---------------- 6) reduce conv3 partials -> pmean/prstd ------------------
__global__ void k_red1() {
    int i = blockIdx.x * 256 + threadIdx.x;
    if (i >= 1024) return;
    int b = i >> 5, g = i & 31;
    float s = 0.f, ss = 0.f;
    #pragma unroll
    for (int cpair = 0; cpair < 2; cpair++) {
        int oc = 2 * g + cpair;
        int m = oc >> 4, rr = oc & 15;
        for (int tile = 0; tile < 8; tile++)
            #pragma unroll
            for (int ngi = 0; ngi < 8; ngi++) {
                int w = ngi * 4 + m;
                float2 v = g_p1[(((size_t)tile * 32 + b) * 32 + w) * 16 + rr];
                s += v.x; ss += v.y;
            }
    }
    float m = s * (1.f / 8192.f);
    float var = ss * (1.f / 8192.f) - m * m;
    g_pmean[i] = m; g_prstd[i] = rsqrtf(var + 1e-5f);
}

// ---------------- 7) final: GN + relu + 1x1 conv to 1 channel (float4) -----
__global__ void k_final(const float* __restrict__ gnw, const float* __restrict__ gnb,
                        const float* __restrict__ w2, const float* __restrict__ b2,
                        float* __restrict__ out) {
    int idx = blockIdx.x * 256 + threadIdx.x;   // 32768 threads, 4 px each
    if (idx >= BATCH * PS / 4) return;
    int b = idx >> 10, p4 = idx & 1023;
    const float4* yb = (const float4*)(g_y + (size_t)b * CC * PS) + p4;
    float bias = b2[0];
    float4 acc = make_float4(bias, bias, bias, bias);
    #pragma unroll 4
    for (int o = 0; o < CC; o++) {
        int bg = b * NGROUP + (o >> 1);
        float m = g_pmean[bg], rs = g_prstd[bg];
        float ga = gnw[o] * rs, be = gnb[o] - m * gnw[o] * rs;
        float wv = w2[o];
        float4 v = yb[(size_t)o * (PS / 4)];
        acc.x += wv * fmaxf(v.x * ga + be, 0.f);
        acc.y += wv * fmaxf(v.y * ga + be, 0.f);
        acc.z += wv * fmaxf(v.z * ga + be, 0.f);
        acc.w += wv * fmaxf(v.w * ga + be, 0.f);
    }
    ((float4*)out)[idx] = acc;
}

// ---------------- launch ----------------------------------------------------
extern "C" void kernel_launch(void* const* d_in, const int* in_sizes, int n_in,
                              void* d_out, int out_size) {
    const float* template_feat = (const float*)d_in[0];
    const float* search_feat   = (const float*)d_in[1];
    const float* w_t    = (const float*)d_in[2];
    const float* gn_t_w = (const float*)d_in[3];
    const float* gn_t_b = (const float*)d_in[4];
    const float* w_s    = (const float*)d_in[5];
    const float* gn_s_w = (const float*)d_in[6];
    const float* gn_s_b = (const float*)d_in[7];
    const float* w_p1   = (const float*)d_in[8];
    const float* gn_p_w = (const float*)d_in[9];
    const float* gn_p_b = (const float*)d_in[10];
    const float* w_p2   = (const float*)d_in[11];
    const float* b_p2   = (const float*)d_in[12];
    float* out = (float*)d_out;

    k_template<<<dim3(BATCH, NGROUP), 128>>>(template_feat, w_t, gn_t_w, gn_t_b);
    k_sgemm<<<dim3(16, BATCH), 512>>>(search_feat, w_s);
    k_red0<<<4, 256>>>();
    k_corr<<<dim3(4, CC, BATCH), 256>>>(gn_s_w, gn_s_b);
    k_conv3<<<dim3(8, BATCH), 1024>>>(w_p1);
    k_red1<<<4, 256>>>();
    k_final<<<128, 256>>>(gn_p_w, gn_p_b, w_p2, b_p2, out);
}

// round 11
// speedup vs baseline: 2.9771x; 1.1606x over previous
#include <cuda_runtime.h>
#include <cuda_bf16.h>

#define BATCH 32
#define CIN   256
#define CC    64
#define PT    196     // 14*14
#define HT    14
#define PS    4096    // 64*64
#define HS    64
#define NGROUP 32     // groups of 2 channels
#define XSZ   5184    // floats per buffer: 8*18*36 == 9*8*72

typedef unsigned long long ull;

// ---------------- packed f32x2 / tf32 / cp.async helpers --------------------
__device__ __forceinline__ ull fma2(ull a, ull b, ull c) {
    ull d;
    asm("fma.rn.f32x2 %0, %1, %2, %3;" : "=l"(d) : "l"(a), "l"(b), "l"(c));
    return d;
}
__device__ __forceinline__ ull pack2(float lo, float hi) {
    ull d;
    asm("mov.b64 %0, {%1, %2};" : "=l"(d) : "f"(lo), "f"(hi));
    return d;
}
__device__ __forceinline__ float2 unpack2(ull v) {
    float2 r;
    asm("mov.b64 {%0, %1}, %2;" : "=f"(r.x), "=f"(r.y) : "l"(v));
    return r;
}
__device__ __forceinline__ float to_tf32(float v) {
    unsigned u;
    asm("cvt.rna.tf32.f32 %0, %1;" : "=r"(u) : "f"(v));
    return __uint_as_float(u);
}
__device__ __forceinline__ void mma_tf32(float* c, const unsigned* a,
                                         unsigned b0, unsigned b1) {
    asm("mma.sync.aligned.m16n8k8.row.col.f32.tf32.tf32.f32 "
        "{%0,%1,%2,%3}, {%4,%5,%6,%7}, {%8,%9}, {%0,%1,%2,%3};"
        : "+f"(c[0]), "+f"(c[1]), "+f"(c[2]), "+f"(c[3])
        : "r"(a[0]), "r"(a[1]), "r"(a[2]), "r"(a[3]), "r"(b0), "r"(b1));
}
__device__ __forceinline__ void cpa4(unsigned dst, const float* src) {
    asm volatile("cp.async.ca.shared.global [%0], [%1], 4;" :: "r"(dst), "l"(src));
}
__device__ __forceinline__ void cpa16(unsigned dst, const float* src) {
    asm volatile("cp.async.cg.shared.global [%0], [%1], 16;" :: "r"(dst), "l"(src));
}
__device__ __forceinline__ void cpa_commit() {
    asm volatile("cp.async.commit_group;");
}
template <int N>
__device__ __forceinline__ void cpa_wait() {
    asm volatile("cp.async.wait_group %0;" :: "n"(N));
}

// ---------------- scratch (device globals; allocation-free) ----------------
__device__ float g_sraw[(size_t)BATCH*CC*PS];   // raw search conv1x1 (pre-GN)
__device__ float g_corr[(size_t)BATCH*CC*PS];   // correlation (tf32-rounded)
__device__ float g_y   [(size_t)BATCH*CC*PS];   // conv3x3 output (pre-GN)
__device__ float g_tker[(size_t)BATCH*CC*49];   // pooled 7x7 template kernels
__device__ float g_tglob[(size_t)BATCH*CC];     // template global means
__device__ float g_wp1t[9*64*64];               // conv3 weights, tf32, [tap][ci][oc]
__device__ float g_smean[BATCH*NGROUP];
__device__ float g_srstd[BATCH*NGROUP];
__device__ float g_pmean[BATCH*NGROUP];
__device__ float g_prstd[BATCH*NGROUP];
__device__ float2 g_p0[512*16*16];              // sgemm stats partials
__device__ float2 g_p1[256*32*16];              // conv3 stats partials

// ---------------- 0) conv3 weight prep: tf32 + [tap][ci][oc] ---------------
__global__ void k_wprep(const float* __restrict__ wp1) {
    int i = blockIdx.x * 1024 + threadIdx.x;
    if (i >= 9 * 64 * 64) return;
    int tap = i >> 12, rem = i & 4095;
    int ciG = rem >> 6, oc = rem & 63;
    g_wp1t[i] = to_tf32(wp1[oc * (CC * 9) + ciG * 9 + tap]);
}

// ---------------- 1) template branch: conv1x1 + GN + relu + pools ----------
__global__ void k_template(const float* __restrict__ tf, const float* __restrict__ wt,
                           const float* __restrict__ gw, const float* __restrict__ gb) {
    int b = blockIdx.x, g = blockIdx.y;
    __shared__ float tv[392];
    __shared__ ull  wsm[256];            // (w[2g][ci], w[2g+1][ci])
    __shared__ float r1[128], r2[128];
    __shared__ float s_mean, s_rstd;
    int tid = threadIdx.x;
    const float* x = tf + (size_t)b * CIN * PT;

    for (int i = tid; i < 256; i += 128)
        wsm[i] = pack2(wt[(g * 2) * CIN + i], wt[(g * 2 + 1) * CIN + i]);
    __syncthreads();

    for (int p = tid; p < PT; p += 128) {
        ull acc = 0ull;
        #pragma unroll 4
        for (int ci = 0; ci < CIN; ci++) {
            float xv = x[ci * PT + p];
            acc = fma2(wsm[ci], pack2(xv, xv), acc);
        }
        float2 r = unpack2(acc);
        tv[p] = r.x; tv[PT + p] = r.y;
    }
    __syncthreads();

    float s = 0.f, ss = 0.f;
    for (int idx = tid; idx < 392; idx += 128) { float v = tv[idx]; s += v; ss += v * v; }
    r1[tid] = s; r2[tid] = ss;
    __syncthreads();
    for (int o = 64; o > 0; o >>= 1) {
        if (tid < o) { r1[tid] += r1[tid + o]; r2[tid] += r2[tid + o]; }
        __syncthreads();
    }
    if (tid == 0) {
        float m = r1[0] * (1.f / 392.f);
        float var = r2[0] * (1.f / 392.f) - m * m;
        s_mean = m; s_rstd = rsqrtf(var + 1e-5f);
    }
    __syncthreads();

    for (int idx = tid; idx < 392; idx += 128) {
        int c = idx / PT;
        float v = (tv[idx] - s_mean) * s_rstd * gw[g * 2 + c] + gb[g * 2 + c];
        tv[idx] = fmaxf(v, 0.f);
    }
    __syncthreads();

    if (tid < 98) {
        int c = tid / 49, cell = tid - c * 49;
        int i = cell / 7, j = cell - i * 7;
        int base = c * PT + (2 * i) * HT + 2 * j;
        float v = 0.25f * (tv[base] + tv[base + 1] + tv[base + HT] + tv[base + HT + 1]);
        g_tker[((size_t)b * CC + g * 2 + c) * 49 + cell] = v;
    }
    if (tid < 2) {
        float acc = 0.f;
        for (int p = 0; p < PT; p++) acc += tv[tid * PT + p];
        g_tglob[(size_t)b * CC + g * 2 + tid] = acc * (1.f / 196.f);
    }
}

// ---------------- 2) search conv1x1 GEMM via mma.sync tf32 -----------------
// grid (16 strips of 256 px, 32 batch), 512 threads (16 warps).
__global__ void __launch_bounds__(512) k_sgemm(const float* __restrict__ sf,
                                               const float* __restrict__ ws) {
    int strip = blockIdx.x, b = blockIdx.y;
    int p0 = strip * 256;
    __shared__ float As[16][72];    // [k][oc], stride 72 -> conflict-free frags
    __shared__ float Bs[16][264];   // [k][px], stride 264 -> conflict-free frags
    int tid = threadIdx.x;
    int w = tid >> 5, lane = tid & 31;
    int gid = lane >> 2, tig = lane & 3;
    int m = w & 3, ng = w >> 2;
    int m0 = m * 16;

    float acc[8][4];
    #pragma unroll
    for (int i = 0; i < 8; i++)
        #pragma unroll
        for (int j = 0; j < 4; j++) acc[i][j] = 0.f;

    const float* xb = sf + (size_t)b * CIN * PS + p0;

    for (int k0 = 0; k0 < CIN; k0 += 16) {
        __syncthreads();
        for (int i = tid; i < 1024; i += 512) {
            int o = i >> 4, k = i & 15;
            As[k][o] = to_tf32(ws[o * CIN + k0 + k]);
        }
        for (int i = tid; i < 1024; i += 512) {
            int k = i >> 6, p4 = i & 63;
            float4 v = ((const float4*)(xb + (size_t)(k0 + k) * PS))[p4];
            v.x = to_tf32(v.x); v.y = to_tf32(v.y);
            v.z = to_tf32(v.z); v.w = to_tf32(v.w);
            ((float4*)&Bs[k][0])[p4] = v;
        }
        __syncthreads();

        #pragma unroll
        for (int ks = 0; ks < 2; ks++) {
            int kb = 8 * ks;
            unsigned a[4];
            a[0] = __float_as_uint(As[kb + tig]    [m0 + gid]);
            a[1] = __float_as_uint(As[kb + tig]    [m0 + gid + 8]);
            a[2] = __float_as_uint(As[kb + tig + 4][m0 + gid]);
            a[3] = __float_as_uint(As[kb + tig + 4][m0 + gid + 8]);
            #pragma unroll
            for (int nt = 0; nt < 8; nt++) {
                int n0 = ng * 64 + nt * 8;
                unsigned b0 = __float_as_uint(Bs[kb + tig]    [n0 + gid]);
                unsigned b1 = __float_as_uint(Bs[kb + tig + 4][n0 + gid]);
                mma_tf32(acc[nt], a, b0, b1);
            }
        }
    }

    float s0 = 0.f, ss0 = 0.f, s1 = 0.f, ss1 = 0.f;
    int oc0 = m0 + gid;
    #pragma unroll
    for (int nt = 0; nt < 8; nt++) {
        int n0 = ng * 64 + nt * 8;
        float c0 = acc[nt][0], c1 = acc[nt][1], c2 = acc[nt][2], c3 = acc[nt][3];
        size_t base = (size_t)p0 + n0 + 2 * tig;
        *(float2*)(g_sraw + ((size_t)b * CC + oc0) * PS + base)     = make_float2(c0, c1);
        *(float2*)(g_sraw + ((size_t)b * CC + oc0 + 8) * PS + base) = make_float2(c2, c3);
        s0 += c0 + c1; ss0 += c0 * c0 + c1 * c1;
        s1 += c2 + c3; ss1 += c2 * c2 + c3 * c3;
    }
    #pragma unroll
    for (int off = 2; off > 0; off >>= 1) {
        s0  += __shfl_down_sync(0xffffffffu, s0,  off, 4);
        ss0 += __shfl_down_sync(0xffffffffu, ss0, off, 4);
        s1  += __shfl_down_sync(0xffffffffu, s1,  off, 4);
        ss1 += __shfl_down_sync(0xffffffffu, ss1, off, 4);
    }
    if (tig == 0) {
        size_t pbase = ((size_t)strip * 32 + b) * 16 + w;
        g_p0[pbase * 16 + gid]     = make_float2(s0, ss0);
        g_p0[pbase * 16 + gid + 8] = make_float2(s1, ss1);
    }
}

// ---------------- 3) reduce sgemm partials -> smean/srstd ------------------
__global__ void k_red0() {
    int i = blockIdx.x * 256 + threadIdx.x;
    if (i >= 1024) return;
    int b = i >> 5, g = i & 31;
    float s = 0.f, ss = 0.f;
    #pragma unroll
    for (int cpair = 0; cpair < 2; cpair++) {
        int oc = 2 * g + cpair;
        int m = oc >> 4, rr = oc & 15;
        for (int tile = 0; tile < 16; tile++)
            #pragma unroll
            for (int ngi = 0; ngi < 4; ngi++) {
                int w = ngi * 4 + m;
                float2 v = g_p0[(((size_t)tile * 32 + b) * 16 + w) * 16 + rr];
                s += v.x; ss += v.y;
            }
    }
    float m = s * (1.f / 8192.f);
    float var = ss * (1.f / 8192.f) - m * m;
    g_smean[i] = m; g_srstd[i] = rsqrtf(var + 1e-5f);
}

// ---------------- 4) corr = global + 7x7 depthwise local -------------------
// stores tf32-rounded values (consumed raw by conv3's cp.async path)
__global__ void __launch_bounds__(256) k_corr(const float* __restrict__ gnw,
                                              const float* __restrict__ gnb) {
    int tile = blockIdx.x, c = blockIdx.y, b = blockIdx.z;
    int ty0 = (tile >> 1) * 32, tx0 = (tile & 1) * 32;
    __shared__ float sm[38 * 38];
    __shared__ float kw[49];
    int tid = threadIdx.x;
    int bg = b * NGROUP + (c >> 1);
    float mean = g_smean[bg], rstd = g_srstd[bg];
    float gamma = gnw[c], beta = gnb[c];
    float tg = g_tglob[(size_t)b * CC + c];
    const float* src = g_sraw + ((size_t)b * CC + c) * PS;

    for (int i = tid; i < 38 * 38; i += 256) {
        int yy = i / 38, xx = i - yy * 38;
        int gy = ty0 + yy - 3, gx = tx0 + xx - 3;
        float v = 0.f;
        if ((unsigned)gy < 64u && (unsigned)gx < 64u) {
            float r = src[gy * HS + gx];
            v = fmaxf((r - mean) * rstd * gamma + beta, 0.f);
        }
        sm[i] = v;
    }
    if (tid < 49) kw[tid] = g_tker[((size_t)b * CC + c) * 49 + tid];
    __syncthreads();

    int p = tid * 4;
    int py = p >> 5, px = p & 31;
    float a0 = 0.f, a1 = 0.f, a2 = 0.f, a3 = 0.f;
    #pragma unroll
    for (int ky = 0; ky < 7; ky++) {
        const float* row = &sm[(py + ky) * 38 + px];
        #pragma unroll
        for (int kx = 0; kx < 7; kx++) {
            float w = kw[ky * 7 + kx];
            a0 += w * row[kx];
            a1 += w * row[kx + 1];
            a2 += w * row[kx + 2];
            a3 += w * row[kx + 3];
        }
    }
    const float* ctr = &sm[(py + 3) * 38 + px + 3];
    a0 += tg * ctr[0]; a1 += tg * ctr[1]; a2 += tg * ctr[2]; a3 += tg * ctr[3];

    float* dst = g_corr + ((size_t)b * CC + c) * PS + (ty0 + py) * HS + tx0 + px;
    *(float4*)dst = make_float4(to_tf32(a0), to_tf32(a1), to_tf32(a2), to_tf32(a3));
}

// ---------------- 5) conv3x3 mma.sync tf32, cp.async double-buffered -------
// grid (8 tiles of 16x32 px, 32 batch), 1024 threads, 83 KB dynamic smem.
__global__ void __launch_bounds__(1024) k_conv3() {
    extern __shared__ float dyn[];
    int tile = blockIdx.x, b = blockIdx.y;
    int ty0 = (tile >> 1) * 16, tx0 = (tile & 1) * 32;
    int tid = threadIdx.x;
    int w = tid >> 5, lane = tid & 31;
    int gid = lane >> 2, tig = lane & 3;
    int m = w & 3, ng = w >> 2;
    int m0 = m * 16;
    int gxl = tx0 - 1;                 // smem xx=0 maps to global col gxl
    int gx0 = (tx0 == 0) ? 0 : gxl;    // first valid col (33 valid cols either way)

    // zero x buffers (halo cells are never written by cp.async)
    for (int i = tid; i < 2 * XSZ; i += 1024) dyn[i] = 0.f;
    __syncthreads();

    auto fill = [&](int cc0, int t) {
        unsigned xs_s = (unsigned)__cvta_generic_to_shared(dyn + t * XSZ);
        unsigned ws_s = (unsigned)__cvta_generic_to_shared(dyn + 2 * XSZ + t * XSZ);
        // x tile: 8 ci x 18 rows x 33 valid cols, 4B cp.async each
        for (int i = tid; i < 8 * 594; i += 1024) {
            int ci = i / 594, rem = i - ci * 594;
            int yy = rem / 33, j = rem - yy * 33;
            int gy = ty0 + yy - 1;
            if ((unsigned)gy < 64u) {
                int gx = gx0 + j;
                int xx = gx - gxl;
                cpa4(xs_s + (unsigned)(ci * 648 + yy * 36 + xx) * 4,
                     g_corr + ((size_t)b * CC + cc0 + ci) * PS + gy * HS + gx);
            }
        }
        // weights: 9 taps x 8 ci x 64 oc, 16B cp.async each
        for (int i = tid; i < 1152; i += 1024) {
            int tap = i >> 7, rem = i & 127;
            int ci = rem >> 4, q = rem & 15;
            cpa16(ws_s + (unsigned)(tap * 576 + ci * 72 + q * 4) * 4,
                  g_wp1t + (tap * 64 + cc0 + ci) * 64 + q * 4);
        }
    };

    float acc[8][4];
    #pragma unroll
    for (int i = 0; i < 8; i++)
        #pragma unroll
        for (int j = 0; j < 4; j++) acc[i][j] = 0.f;

    fill(0, 0);
    cpa_commit();

    for (int c = 0; c < 8; c++) {
        if (c < 7) { fill((c + 1) * 8, (c + 1) & 1); cpa_commit(); }
        if (c < 7) cpa_wait<1>(); else cpa_wait<0>();
        __syncthreads();

        const float* xsb = dyn + (c & 1) * XSZ;
        const float* wsb = dyn + 2 * XSZ + (c & 1) * XSZ;

        #pragma unroll
        for (int tap = 0; tap < 9; tap++) {
            int dy = tap / 3, dx = tap - 3 * (tap / 3);
            unsigned a[4];
            a[0] = __float_as_uint(wsb[tap * 576 + tig * 72 + m0 + gid]);
            a[1] = __float_as_uint(wsb[tap * 576 + tig * 72 + m0 + gid + 8]);
            a[2] = __float_as_uint(wsb[tap * 576 + (tig + 4) * 72 + m0 + gid]);
            a[3] = __float_as_uint(wsb[tap * 576 + (tig + 4) * 72 + m0 + gid + 8]);
            #pragma unroll
            for (int nt = 0; nt < 8; nt++) {
                int n0 = ng * 64 + nt * 8;
                int y0 = n0 >> 5, x0 = n0 & 31;
                unsigned b0 = __float_as_uint(
                    xsb[tig * 648 + (y0 + dy) * 36 + x0 + gid + dx]);
                unsigned b1 = __float_as_uint(
                    xsb[(tig + 4) * 648 + (y0 + dy) * 36 + x0 + gid + dx]);
                mma_tf32(acc[nt], a, b0, b1);
            }
        }
        __syncthreads();
    }

    // store fp32 + fused GN stats partials
    float s0 = 0.f, ss0 = 0.f, s1 = 0.f, ss1 = 0.f;
    int oc0 = m0 + gid;
    #pragma unroll
    for (int nt = 0; nt < 8; nt++) {
        int n0 = ng * 64 + nt * 8;
        int y0 = n0 >> 5, x0 = n0 & 31;
        float c0 = acc[nt][0], c1 = acc[nt][1], c2 = acc[nt][2], c3 = acc[nt][3];
        size_t base = (size_t)(ty0 + y0) * HS + tx0 + x0 + 2 * tig;
        *(float2*)(g_y + ((size_t)b * CC + oc0) * PS + base)     = make_float2(c0, c1);
        *(float2*)(g_y + ((size_t)b * CC + oc0 + 8) * PS + base) = make_float2(c2, c3);
        s0 += c0 + c1; ss0 += c0 * c0 + c1 * c1;
        s1 += c2 + c3; ss1 += c2 * c2 + c3 * c3;
    }
    #pragma unroll
    for (int off = 2; off > 0; off >>= 1) {
        s0  += __shfl_down_sync(0xffffffffu, s0,  off, 4);
        ss0 += __shfl_down_sync(0xffffffffu, ss0, off, 4);
        s1  += __shfl_down_sync(0xffffffffu, s1,  off, 4);
        ss1 += __shfl_down_sync(0xffffffffu, ss1, off, 4);
    }
    if (tig == 0) {
        size_t pbase = ((size_t)tile * 32 + b) * 32 + w;
        g_p1[pbase * 16 + gid]     = make_float2(s0, ss0);
        g_p1[pbase * 16 + gid + 8] = make_float2(s1, ss1);
    }
}

// ---------------- 6) reduce conv3 partials -> pmean/prstd ------------------
__global__ void k_red1() {
    int i = blockIdx.x * 256 + threadIdx.x;
    if (i >= 1024) return;
    int b = i >> 5, g = i & 31;
    float s = 0.f, ss = 0.f;
    #pragma unroll
    for (int cpair = 0; cpair < 2; cpair++) {
        int oc = 2 * g + cpair;
        int m = oc >> 4, rr = oc & 15;
        for (int tile = 0; tile < 8; tile++)
            #pragma unroll
            for (int ngi = 0; ngi < 8; ngi++) {
                int w = ngi * 4 + m;
                float2 v = g_p1[(((size_t)tile * 32 + b) * 32 + w) * 16 + rr];
                s += v.x; ss += v.y;
            }
    }
    float m = s * (1.f / 8192.f);
    float var = ss * (1.f / 8192.f) - m * m;
    g_pmean[i] = m; g_prstd[i] = rsqrtf(var + 1e-5f);
}

// ---------------- 7) final: GN + relu + 1x1 conv to 1 channel (float4) -----
__global__ void __launch_bounds__(128) k_final(const float* __restrict__ gnw,
                                               const float* __restrict__ gnb,
                                               const float* __restrict__ w2,
                                               const float* __restrict__ b2,
                                               float* __restrict__ out) {
    int idx = blockIdx.x * 128 + threadIdx.x;   // 32768 threads, 4 px each
    if (idx >= BATCH * PS / 4) return;
    int b = idx >> 10, p4 = idx & 1023;
    const float4* yb = (const float4*)(g_y + (size_t)b * CC * PS) + p4;
    float bias = b2[0];
    float4 acc = make_float4(bias, bias, bias, bias);
    #pragma unroll 8
    for (int o = 0; o < CC; o++) {
        int bg = b * NGROUP + (o >> 1);
        float m = g_pmean[bg], rs = g_prstd[bg];
        float ga = gnw[o] * rs, be = gnb[o] - m * gnw[o] * rs;
        float wv = w2[o];
        float4 v = yb[(size_t)o * (PS / 4)];
        acc.x += wv * fmaxf(v.x * ga + be, 0.f);
        acc.y += wv * fmaxf(v.y * ga + be, 0.f);
        acc.z += wv * fmaxf(v.z * ga + be, 0.f);
        acc.w += wv * fmaxf(v.w * ga + be, 0.f);
    }
    ((float4*)out)[idx] = acc;
}

// ---------------- launch ----------------------------------------------------
extern "C" void kernel_launch(void* const* d_in, const int* in_sizes, int n_in,
                              void* d_out, int out_size) {
    const float* template_feat = (const float*)d_in[0];
    const float* search_feat   = (const float*)d_in[1];
    const float* w_t    = (const float*)d_in[2];
    const float* gn_t_w = (const float*)d_in[3];
    const float* gn_t_b = (const float*)d_in[4];
    const float* w_s    = (const float*)d_in[5];
    const float* gn_s_w = (const float*)d_in[6];
    const float* gn_s_b = (const float*)d_in[7];
    const float* w_p1   = (const float*)d_in[8];
    const float* gn_p_w = (const float*)d_in[9];
    const float* gn_p_b = (const float*)d_in[10];
    const float* w_p2   = (const float*)d_in[11];
    const float* b_p2   = (const float*)d_in[12];
    float* out = (float*)d_out;

    const int conv3_smem = 4 * XSZ * 4;   // 82944 B
    cudaFuncSetAttribute(k_conv3, cudaFuncAttributeMaxDynamicSharedMemorySize,
                         conv3_smem);

    k_wprep<<<36, 1024>>>(w_p1);
    k_template<<<dim3(BATCH, NGROUP), 128>>>(template_feat, w_t, gn_t_w, gn_t_b);
    k_sgemm<<<dim3(16, BATCH), 512>>>(search_feat, w_s);
    k_red0<<<4, 256>>>();
    k_corr<<<dim3(4, CC, BATCH), 256>>>(gn_s_w, gn_s_b);
    k_conv3<<<dim3(8, BATCH), 1024, conv3_smem>>>();
    k_red1<<<4, 256>>>();
    k_final<<<256, 128>>>(gn_p_w, gn_p_b, w_p2, b_p2, out);
}

// round 12
// speedup vs baseline: 3.4647x; 1.1638x over previous
#include <cuda_runtime.h>
#include <cuda_bf16.h>

#define BATCH 32
#define CIN   256
#define CC    64
#define PT    196     // 14*14
#define HT    14
#define PS    4096    // 64*64
#define HS    64
#define NGROUP 32     // groups of 2 channels
#define XSZ   5184    // conv3 floats per buffer: 8*18*36 == 9*8*72

typedef unsigned long long ull;

// ---------------- packed f32x2 / tf32 / cp.async helpers --------------------
__device__ __forceinline__ ull fma2(ull a, ull b, ull c) {
    ull d;
    asm("fma.rn.f32x2 %0, %1, %2, %3;" : "=l"(d) : "l"(a), "l"(b), "l"(c));
    return d;
}
__device__ __forceinline__ ull pack2(float lo, float hi) {
    ull d;
    asm("mov.b64 %0, {%1, %2};" : "=l"(d) : "f"(lo), "f"(hi));
    return d;
}
__device__ __forceinline__ float2 unpack2(ull v) {
    float2 r;
    asm("mov.b64 {%0, %1}, %2;" : "=f"(r.x), "=f"(r.y) : "l"(v));
    return r;
}
__device__ __forceinline__ float to_tf32(float v) {
    unsigned u;
    asm("cvt.rna.tf32.f32 %0, %1;" : "=r"(u) : "f"(v));
    return __uint_as_float(u);
}
__device__ __forceinline__ void mma_tf32(float* c, const unsigned* a,
                                         unsigned b0, unsigned b1) {
    asm("mma.sync.aligned.m16n8k8.row.col.f32.tf32.tf32.f32 "
        "{%0,%1,%2,%3}, {%4,%5,%6,%7}, {%8,%9}, {%0,%1,%2,%3};"
        : "+f"(c[0]), "+f"(c[1]), "+f"(c[2]), "+f"(c[3])
        : "r"(a[0]), "r"(a[1]), "r"(a[2]), "r"(a[3]), "r"(b0), "r"(b1));
}
__device__ __forceinline__ void cpa4(unsigned dst, const float* src) {
    asm volatile("cp.async.ca.shared.global [%0], [%1], 4;" :: "r"(dst), "l"(src));
}
__device__ __forceinline__ void cpa16(unsigned dst, const float* src) {
    asm volatile("cp.async.cg.shared.global [%0], [%1], 16;" :: "r"(dst), "l"(src));
}
__device__ __forceinline__ void cpa_commit() {
    asm volatile("cp.async.commit_group;");
}
template <int N>
__device__ __forceinline__ void cpa_wait() {
    asm volatile("cp.async.wait_group %0;" :: "n"(N));
}

// ---------------- scratch (device globals; allocation-free) ----------------
__device__ float g_sraw[(size_t)BATCH*CC*PS];   // raw search conv1x1 (pre-GN)
__device__ float g_corr[(size_t)BATCH*CC*PS];   // correlation (tf32-rounded)
__device__ float g_y   [(size_t)BATCH*CC*PS];   // conv3x3 output (pre-GN)
__device__ float g_tker[(size_t)BATCH*CC*49];   // pooled 7x7 template kernels
__device__ float g_tglob[(size_t)BATCH*CC];     // template global means
__device__ float g_wp1t[9*64*64];               // conv3 weights, tf32, [tap][ci][oc]
__device__ float g_wst [256*64];                // w_s, tf32, [k][oc]
__device__ float g_smean[BATCH*NGROUP];
__device__ float g_srstd[BATCH*NGROUP];
__device__ float g_pmean[BATCH*NGROUP];
__device__ float g_prstd[BATCH*NGROUP];
__device__ float2 g_p0[512*16*16];              // sgemm stats partials
__device__ float2 g_p1[256*32*16];              // conv3 stats partials

// ---------------- 0) weight prep: tf32 + transposes ------------------------
__global__ void k_wprep(const float* __restrict__ wp1, const float* __restrict__ ws) {
    int i = blockIdx.x * 1024 + threadIdx.x;
    if (i < 9 * 64 * 64) {
        int tap = i >> 12, rem = i & 4095;
        int ciG = rem >> 6, oc = rem & 63;
        g_wp1t[i] = to_tf32(wp1[oc * (CC * 9) + ciG * 9 + tap]);
    } else {
        int j = i - 9 * 64 * 64;
        if (j < 256 * 64) {
            int k = j >> 6, oc = j & 63;
            g_wst[j] = to_tf32(ws[oc * CIN + k]);
        }
    }
}

// ---------------- 1) template branch: conv1x1 + GN + relu + pools ----------
__global__ void k_template(const float* __restrict__ tf, const float* __restrict__ wt,
                           const float* __restrict__ gw, const float* __restrict__ gb) {
    int b = blockIdx.x, g = blockIdx.y;
    __shared__ float tv[392];
    __shared__ ull  wsm[256];            // (w[2g][ci], w[2g+1][ci])
    __shared__ float r1[128], r2[128];
    __shared__ float s_mean, s_rstd;
    int tid = threadIdx.x;
    const float* x = tf + (size_t)b * CIN * PT;

    for (int i = tid; i < 256; i += 128)
        wsm[i] = pack2(wt[(g * 2) * CIN + i], wt[(g * 2 + 1) * CIN + i]);
    __syncthreads();

    for (int p = tid; p < PT; p += 128) {
        ull acc = 0ull;
        #pragma unroll 4
        for (int ci = 0; ci < CIN; ci++) {
            float xv = x[ci * PT + p];
            acc = fma2(wsm[ci], pack2(xv, xv), acc);
        }
        float2 r = unpack2(acc);
        tv[p] = r.x; tv[PT + p] = r.y;
    }
    __syncthreads();

    float s = 0.f, ss = 0.f;
    for (int idx = tid; idx < 392; idx += 128) { float v = tv[idx]; s += v; ss += v * v; }
    r1[tid] = s; r2[tid] = ss;
    __syncthreads();
    for (int o = 64; o > 0; o >>= 1) {
        if (tid < o) { r1[tid] += r1[tid + o]; r2[tid] += r2[tid + o]; }
        __syncthreads();
    }
    if (tid == 0) {
        float m = r1[0] * (1.f / 392.f);
        float var = r2[0] * (1.f / 392.f) - m * m;
        s_mean = m; s_rstd = rsqrtf(var + 1e-5f);
    }
    __syncthreads();

    for (int idx = tid; idx < 392; idx += 128) {
        int c = idx / PT;
        float v = (tv[idx] - s_mean) * s_rstd * gw[g * 2 + c] + gb[g * 2 + c];
        tv[idx] = fmaxf(v, 0.f);
    }
    __syncthreads();

    if (tid < 98) {
        int c = tid / 49, cell = tid - c * 49;
        int i = cell / 7, j = cell - i * 7;
        int base = c * PT + (2 * i) * HT + 2 * j;
        float v = 0.25f * (tv[base] + tv[base + 1] + tv[base + HT] + tv[base + HT + 1]);
        g_tker[((size_t)b * CC + g * 2 + c) * 49 + cell] = v;
    }
    if (tid < 2) {
        float acc = 0.f;
        for (int p = 0; p < PT; p++) acc += tv[tid * PT + p];
        g_tglob[(size_t)b * CC + g * 2 + tid] = acc * (1.f / 196.f);
    }
}

// ---------------- 2) search conv1x1 GEMM, tf32 mma + cp.async pipeline -----
// grid (16 strips of 256 px, 32 batch), 512 threads (16 warps).
// A pre-rounded (rna) from g_wst; B raw fp32 (HW-truncated to tf32 by mma).
__global__ void __launch_bounds__(512) k_sgemm(const float* __restrict__ sf) {
    __shared__ float As[2][16 * 72];    // [k][oc], stride 72
    __shared__ float Bs[2][16 * 264];   // [k][px], stride 264
    int strip = blockIdx.x, b = blockIdx.y;
    int p0 = strip * 256;
    int tid = threadIdx.x;
    int w = tid >> 5, lane = tid & 31;
    int gid = lane >> 2, tig = lane & 3;
    int m = w & 3, ng = w >> 2;
    int m0 = m * 16;

    const float* xb = sf + (size_t)b * CIN * PS + p0;

    auto fill = [&](int k0, int t) {
        unsigned a_s = (unsigned)__cvta_generic_to_shared(As[t]);
        unsigned b_s = (unsigned)__cvta_generic_to_shared(Bs[t]);
        // A: 16 k x 64 oc = 256 16B ops
        for (int i = tid; i < 256; i += 512) {
            int k = i >> 4, q = i & 15;
            cpa16(a_s + (unsigned)(k * 72 + q * 4) * 4,
                  g_wst + (k0 + k) * 64 + q * 4);
        }
        // B: 16 k x 256 px = 1024 16B ops
        for (int i = tid; i < 1024; i += 512) {
            int k = i >> 6, p4 = i & 63;
            cpa16(b_s + (unsigned)(k * 264 + p4 * 4) * 4,
                  xb + (size_t)(k0 + k) * PS + p4 * 4);
        }
    };

    float acc[8][4];
    #pragma unroll
    for (int i = 0; i < 8; i++)
        #pragma unroll
        for (int j = 0; j < 4; j++) acc[i][j] = 0.f;

    fill(0, 0);
    cpa_commit();

    for (int c = 0; c < 16; c++) {
        if (c < 15) { fill((c + 1) * 16, (c + 1) & 1); cpa_commit(); }
        if (c < 15) cpa_wait<1>(); else cpa_wait<0>();
        __syncthreads();

        const float* Ab = As[c & 1];
        const float* Bb = Bs[c & 1];

        #pragma unroll
        for (int ks = 0; ks < 2; ks++) {
            int kb = 8 * ks;
            unsigned a[4];
            a[0] = __float_as_uint(Ab[(kb + tig) * 72 + m0 + gid]);
            a[1] = __float_as_uint(Ab[(kb + tig) * 72 + m0 + gid + 8]);
            a[2] = __float_as_uint(Ab[(kb + tig + 4) * 72 + m0 + gid]);
            a[3] = __float_as_uint(Ab[(kb + tig + 4) * 72 + m0 + gid + 8]);
            #pragma unroll
            for (int nt = 0; nt < 8; nt++) {
                int n0 = ng * 64 + nt * 8;
                unsigned b0 = __float_as_uint(Bb[(kb + tig) * 264 + n0 + gid]);
                unsigned b1 = __float_as_uint(Bb[(kb + tig + 4) * 264 + n0 + gid]);
                mma_tf32(acc[nt], a, b0, b1);
            }
        }
        __syncthreads();
    }

    float s0 = 0.f, ss0 = 0.f, s1 = 0.f, ss1 = 0.f;
    int oc0 = m0 + gid;
    #pragma unroll
    for (int nt = 0; nt < 8; nt++) {
        int n0 = ng * 64 + nt * 8;
        float c0 = acc[nt][0], c1 = acc[nt][1], c2 = acc[nt][2], c3 = acc[nt][3];
        size_t base = (size_t)p0 + n0 + 2 * tig;
        *(float2*)(g_sraw + ((size_t)b * CC + oc0) * PS + base)     = make_float2(c0, c1);
        *(float2*)(g_sraw + ((size_t)b * CC + oc0 + 8) * PS + base) = make_float2(c2, c3);
        s0 += c0 + c1; ss0 += c0 * c0 + c1 * c1;
        s1 += c2 + c3; ss1 += c2 * c2 + c3 * c3;
    }
    #pragma unroll
    for (int off = 2; off > 0; off >>= 1) {
        s0  += __shfl_down_sync(0xffffffffu, s0,  off, 4);
        ss0 += __shfl_down_sync(0xffffffffu, ss0, off, 4);
        s1  += __shfl_down_sync(0xffffffffu, s1,  off, 4);
        ss1 += __shfl_down_sync(0xffffffffu, ss1, off, 4);
    }
    if (tig == 0) {
        size_t pbase = ((size_t)strip * 32 + b) * 16 + w;
        g_p0[pbase * 16 + gid]     = make_float2(s0, ss0);
        g_p0[pbase * 16 + gid + 8] = make_float2(s1, ss1);
    }
}

// ---------------- 3) parallel reduce partials -> mean/rstd -----------------
// warp per output (b,g): 32 lanes x 4 partials + shfl. grid 128 x 256.
__global__ void __launch_bounds__(256) k_red(int which) {
    int gidx = blockIdx.x * 256 + threadIdx.x;
    int out = gidx >> 5;
    int lane = gidx & 31;
    if (out >= 1024) return;
    int b = out >> 5, g = out & 31;
    const float2* part = which ? g_p1 : g_p0;
    int wdim = which ? 32 : 16;
    int ngi_bits = which ? 3 : 2;
    float s = 0.f, ss = 0.f;
    #pragma unroll
    for (int k = 0; k < 4; k++) {
        int t = lane + 32 * k;               // 0..127
        int cpair = t & 1, u = t >> 1;       // u 0..63
        int ngi = u & ((1 << ngi_bits) - 1);
        int tile = u >> ngi_bits;
        int oc = 2 * g + cpair, m = oc >> 4, rr = oc & 15;
        int w = ngi * 4 + m;
        float2 v = part[(((size_t)tile * 32 + b) * wdim + w) * 16 + rr];
        s += v.x; ss += v.y;
    }
    #pragma unroll
    for (int off = 16; off > 0; off >>= 1) {
        s  += __shfl_down_sync(0xffffffffu, s,  off);
        ss += __shfl_down_sync(0xffffffffu, ss, off);
    }
    if (lane == 0) {
        float m = s * (1.f / 8192.f);
        float var = ss * (1.f / 8192.f) - m * m;
        if (which) { g_pmean[out] = m; g_prstd[out] = rsqrtf(var + 1e-5f); }
        else       { g_smean[out] = m; g_srstd[out] = rsqrtf(var + 1e-5f); }
    }
}

// ---------------- 4) corr = global + 7x7 depthwise local -------------------
// stores tf32-rounded values (consumed raw by conv3's cp.async path)
__global__ void __launch_bounds__(256) k_corr(const float* __restrict__ gnw,
                                              const float* __restrict__ gnb) {
    int tile = blockIdx.x, c = blockIdx.y, b = blockIdx.z;
    int ty0 = (tile >> 1) * 32, tx0 = (tile & 1) * 32;
    __shared__ float sm[38 * 38];
    __shared__ float kw[49];
    int tid = threadIdx.x;
    int bg = b * NGROUP + (c >> 1);
    float mean = g_smean[bg], rstd = g_srstd[bg];
    float gamma = gnw[c], beta = gnb[c];
    float tg = g_tglob[(size_t)b * CC + c];
    const float* src = g_sraw + ((size_t)b * CC + c) * PS;

    for (int i = tid; i < 38 * 38; i += 256) {
        int yy = i / 38, xx = i - yy * 38;
        int gy = ty0 + yy - 3, gx = tx0 + xx - 3;
        float v = 0.f;
        if ((unsigned)gy < 64u && (unsigned)gx < 64u) {
            float r = src[gy * HS + gx];
            v = fmaxf((r - mean) * rstd * gamma + beta, 0.f);
        }
        sm[i] = v;
    }
    if (tid < 49) kw[tid] = g_tker[((size_t)b * CC + c) * 49 + tid];
    __syncthreads();

    int p = tid * 4;
    int py = p >> 5, px = p & 31;
    float a0 = 0.f, a1 = 0.f, a2 = 0.f, a3 = 0.f;
    #pragma unroll
    for (int ky = 0; ky < 7; ky++) {
        const float* row = &sm[(py + ky) * 38 + px];
        #pragma unroll
        for (int kx = 0; kx < 7; kx++) {
            float w = kw[ky * 7 + kx];
            a0 += w * row[kx];
            a1 += w * row[kx + 1];
            a2 += w * row[kx + 2];
            a3 += w * row[kx + 3];
        }
    }
    const float* ctr = &sm[(py + 3) * 38 + px + 3];
    a0 += tg * ctr[0]; a1 += tg * ctr[1]; a2 += tg * ctr[2]; a3 += tg * ctr[3];

    float* dst = g_corr + ((size_t)b * CC + c) * PS + (ty0 + py) * HS + tx0 + px;
    *(float4*)dst = make_float4(to_tf32(a0), to_tf32(a1), to_tf32(a2), to_tf32(a3));
}

// ---------------- 5) conv3x3 mma.sync tf32, cp.async double-buffered -------
// grid (8 tiles of 16x32 px, 32 batch), 1024 threads, 83 KB dynamic smem.
__global__ void __launch_bounds__(1024) k_conv3() {
    extern __shared__ float dyn[];
    int tile = blockIdx.x, b = blockIdx.y;
    int ty0 = (tile >> 1) * 16, tx0 = (tile & 1) * 32;
    int tid = threadIdx.x;
    int w = tid >> 5, lane = tid & 31;
    int gid = lane >> 2, tig = lane & 3;
    int m = w & 3, ng = w >> 2;
    int m0 = m * 16;
    int gxl = tx0 - 1;                 // smem xx=0 maps to global col gxl
    int gx0 = (tx0 == 0) ? 0 : gxl;    // first valid col (33 valid cols either way)

    // zero x buffers (halo cells are never written by cp.async)
    for (int i = tid; i < 2 * XSZ; i += 1024) dyn[i] = 0.f;
    __syncthreads();

    auto fill = [&](int cc0, int t) {
        unsigned xs_s = (unsigned)__cvta_generic_to_shared(dyn + t * XSZ);
        unsigned ws_s = (unsigned)__cvta_generic_to_shared(dyn + 2 * XSZ + t * XSZ);
        for (int i = tid; i < 8 * 594; i += 1024) {
            int ci = i / 594, rem = i - ci * 594;
            int yy = rem / 33, j = rem - yy * 33;
            int gy = ty0 + yy - 1;
            if ((unsigned)gy < 64u) {
                int gx = gx0 + j;
                int xx = gx - gxl;
                cpa4(xs_s + (unsigned)(ci * 648 + yy * 36 + xx) * 4,
                     g_corr + ((size_t)b * CC + cc0 + ci) * PS + gy * HS + gx);
            }
        }
        for (int i = tid; i < 1152; i += 1024) {
            int tap = i >> 7, rem = i & 127;
            int ci = rem >> 4, q = rem & 15;
            cpa16(ws_s + (unsigned)(tap * 576 + ci * 72 + q * 4) * 4,
                  g_wp1t + (tap * 64 + cc0 + ci) * 64 + q * 4);
        }
    };

    float acc[8][4];
    #pragma unroll
    for (int i = 0; i < 8; i++)
        #pragma unroll
        for (int j = 0; j < 4; j++) acc[i][j] = 0.f;

    fill(0, 0);
    cpa_commit();

    for (int c = 0; c < 8; c++) {
        if (c < 7) { fill((c + 1) * 8, (c + 1) & 1); cpa_commit(); }
        if (c < 7) cpa_wait<1>(); else cpa_wait<0>();
        __syncthreads();

        const float* xsb = dyn + (c & 1) * XSZ;
        const float* wsb = dyn + 2 * XSZ + (c & 1) * XSZ;

        #pragma unroll
        for (int tap = 0; tap < 9; tap++) {
            int dy = tap / 3, dx = tap - 3 * (tap / 3);
            unsigned a[4];
            a[0] = __float_as_uint(wsb[tap * 576 + tig * 72 + m0 + gid]);
            a[1] = __float_as_uint(wsb[tap * 576 + tig * 72 + m0 + gid + 8]);
            a[2] = __float_as_uint(wsb[tap * 576 + (tig + 4) * 72 + m0 + gid]);
            a[3] = __float_as_uint(wsb[tap * 576 + (tig + 4) * 72 + m0 + gid + 8]);
            #pragma unroll
            for (int nt = 0; nt < 8; nt++) {
                int n0 = ng * 64 + nt * 8;
                int y0 = n0 >> 5, x0 = n0 & 31;
                unsigned b0 = __float_as_uint(
                    xsb[tig * 648 + (y0 + dy) * 36 + x0 + gid + dx]);
                unsigned b1 = __float_as_uint(
                    xsb[(tig + 4) * 648 + (y0 + dy) * 36 + x0 + gid + dx]);
                mma_tf32(acc[nt], a, b0, b1);
            }
        }
        __syncthreads();
    }

    // store fp32 + fused GN stats partials
    float s0 = 0.f, ss0 = 0.f, s1 = 0.f, ss1 = 0.f;
    int oc0 = m0 + gid;
    #pragma unroll
    for (int nt = 0; nt < 8; nt++) {
        int n0 = ng * 64 + nt * 8;
        int y0 = n0 >> 5, x0 = n0 & 31;
        float c0 = acc[nt][0], c1 = acc[nt][1], c2 = acc[nt][2], c3 = acc[nt][3];
        size_t base = (size_t)(ty0 + y0) * HS + tx0 + x0 + 2 * tig;
        *(float2*)(g_y + ((size_t)b * CC + oc0) * PS + base)     = make_float2(c0, c1);
        *(float2*)(g_y + ((size_t)b * CC + oc0 + 8) * PS + base) = make_float2(c2, c3);
        s0 += c0 + c1; ss0 += c0 * c0 + c1 * c1;
        s1 += c2 + c3; ss1 += c2 * c2 + c3 * c3;
    }
    #pragma unroll
    for (int off = 2; off > 0; off >>= 1) {
        s0  += __shfl_down_sync(0xffffffffu, s0,  off, 4);
        ss0 += __shfl_down_sync(0xffffffffu, ss0, off, 4);
        s1  += __shfl_down_sync(0xffffffffu, s1,  off, 4);
        ss1 += __shfl_down_sync(0xffffffffu, ss1, off, 4);
    }
    if (tig == 0) {
        size_t pbase = ((size_t)tile * 32 + b) * 32 + w;
        g_p1[pbase * 16 + gid]     = make_float2(s0, ss0);
        g_p1[pbase * 16 + gid + 8] = make_float2(s1, ss1);
    }
}

// ---------------- 7) final: GN + relu + 1x1 conv to 1 channel (float4) -----
__global__ void __launch_bounds__(128) k_final(const float* __restrict__ gnw,
                                               const float* __restrict__ gnb,
                                               const float* __restrict__ w2,
                                               const float* __restrict__ b2,
                                               float* __restrict__ out) {
    int idx = blockIdx.x * 128 + threadIdx.x;   // 32768 threads, 4 px each
    if (idx >= BATCH * PS / 4) return;
    int b = idx >> 10, p4 = idx & 1023;
    const float4* yb = (const float4*)(g_y + (size_t)b * CC * PS) + p4;
    float bias = b2[0];
    float4 acc = make_float4(bias, bias, bias, bias);
    #pragma unroll 8
    for (int o = 0; o < CC; o++) {
        int bg = b * NGROUP + (o >> 1);
        float m = g_pmean[bg], rs = g_prstd[bg];
        float ga = gnw[o] * rs, be = gnb[o] - m * gnw[o] * rs;
        float wv = w2[o];
        float4 v = yb[(size_t)o * (PS / 4)];
        acc.x += wv * fmaxf(v.x * ga + be, 0.f);
        acc.y += wv * fmaxf(v.y * ga + be, 0.f);
        acc.z += wv * fmaxf(v.z * ga + be, 0.f);
        acc.w += wv * fmaxf(v.w * ga + be, 0.f);
    }
    ((float4*)out)[idx] = acc;
}

// ---------------- launch ----------------------------------------------------
extern "C" void kernel_launch(void* const* d_in, const int* in_sizes, int n_in,
                              void* d_out, int out_size) {
    const float* template_feat = (const float*)d_in[0];
    const float* search_feat   = (const float*)d_in[1];
    const float* w_t    = (const float*)d_in[2];
    const float* gn_t_w = (const float*)d_in[3];
    const float* gn_t_b = (const float*)d_in[4];
    const float* w_s    = (const float*)d_in[5];
    const float* gn_s_w = (const float*)d_in[6];
    const float* gn_s_b = (const float*)d_in[7];
    const float* w_p1   = (const float*)d_in[8];
    const float* gn_p_w = (const float*)d_in[9];
    const float* gn_p_b = (const float*)d_in[10];
    const float* w_p2   = (const float*)d_in[11];
    const float* b_p2   = (const float*)d_in[12];
    float* out = (float*)d_out;

    const int conv3_smem = 4 * XSZ * 4;   // 82944 B
    cudaFuncSetAttribute(k_conv3, cudaFuncAttributeMaxDynamicSharedMemorySize,
                         conv3_smem);

    k_wprep<<<52, 1024>>>(w_p1, w_s);
    k_template<<<dim3(BATCH, NGROUP), 128>>>(template_feat, w_t, gn_t_w, gn_t_b);
    k_sgemm<<<dim3(16, BATCH), 512>>>(search_feat);
    k_red<<<128, 256>>>(0);
    k_corr<<<dim3(4, CC, BATCH), 256>>>(gn_s_w, gn_s_b);
    k_conv3<<<dim3(8, BATCH), 1024, conv3_smem>>>();
    k_red<<<128, 256>>>(1);
    k_final<<<256, 128>>>(gn_p_w, gn_p_b, w_p2, b_p2, out);
}